// round 1
// baseline (speedup 1.0000x reference)
#include <cuda_runtime.h>

#define BB 4
#define SEQ 4096
#define DM 1024
#define DK 64
#define MTOT (BB*SEQ)

// Scratch (device globals — allocation-free)
__device__ float g_qh[MTOT*DK];
__device__ float g_kh[MTOT*DK];
__device__ float g_vh[MTOT*DK];
__device__ float g_ao[MTOT*DK];

// ---------------------------------------------------------------------------
// Projection: y[M,64] = (x[M,1024] @ W[64,1024]^T + b) * prescale
// 64x64 tile, 256 threads, 4x4 micro-tile.
// ---------------------------------------------------------------------------
__global__ __launch_bounds__(256) void proj_kernel(
    const float* __restrict__ x, const float* __restrict__ W,
    const float* __restrict__ bias, float* __restrict__ y, float prescale)
{
    __shared__ float Xs[64][65];
    __shared__ float Ws[64][65];
    const int row0 = blockIdx.x * 64;
    const int tx = threadIdx.x & 15;
    const int ty = threadIdx.x >> 4;
    float acc[4][4] = {};

    for (int k0 = 0; k0 < DM; k0 += 64) {
        for (int i = threadIdx.x; i < 64*16; i += 256) {
            int r = i >> 4, c4 = (i & 15) << 2;
            float4 xv = *(const float4*)(x + (size_t)(row0 + r)*DM + k0 + c4);
            Xs[r][c4+0] = xv.x; Xs[r][c4+1] = xv.y;
            Xs[r][c4+2] = xv.z; Xs[r][c4+3] = xv.w;
            float4 wv = *(const float4*)(W + (size_t)r*DM + k0 + c4);
            Ws[r][c4+0] = wv.x; Ws[r][c4+1] = wv.y;
            Ws[r][c4+2] = wv.z; Ws[r][c4+3] = wv.w;
        }
        __syncthreads();
        #pragma unroll
        for (int kk = 0; kk < 64; kk++) {
            float a[4], b[4];
            #pragma unroll
            for (int i = 0; i < 4; i++) a[i] = Xs[ty*4+i][kk];
            #pragma unroll
            for (int j = 0; j < 4; j++) b[j] = Ws[tx*4+j][kk];
            #pragma unroll
            for (int i = 0; i < 4; i++)
                #pragma unroll
                for (int j = 0; j < 4; j++)
                    acc[i][j] += a[i]*b[j];
        }
        __syncthreads();
    }

    #pragma unroll
    for (int i = 0; i < 4; i++) {
        int r = row0 + ty*4 + i;
        float4 o;
        o.x = (acc[i][0] + bias[tx*4+0]) * prescale;
        o.y = (acc[i][1] + bias[tx*4+1]) * prescale;
        o.z = (acc[i][2] + bias[tx*4+2]) * prescale;
        o.w = (acc[i][3] + bias[tx*4+3]) * prescale;
        *(float4*)(y + (size_t)r*DK + tx*4) = o;
    }
}

// ---------------------------------------------------------------------------
// Flash attention: CTA = (64 queries, 1 batch). Online softmax over 64-key
// tiles. O accumulator in registers (4x4 per thread).
// ---------------------------------------------------------------------------
__global__ __launch_bounds__(256) void attn_kernel(const int* __restrict__ mask)
{
    extern __shared__ float sm[];
    float (*Qs)[65] = (float(*)[65])sm;                       // 64*65
    float (*Ks)[65] = (float(*)[65])(sm + 64*65);             // 64*65
    float (*Vs)[68] = (float(*)[68])(sm + 2*64*65);           // 64*68 (16B-aligned rows)
    float (*Ps)[65] = (float(*)[65])(sm + 2*64*65 + 64*68);   // 64*65
    __shared__ float mrow[64], lrow[64], crow[64];

    const int b  = blockIdx.y;
    const int q0 = blockIdx.x * 64;
    const float* qh = g_qh + (size_t)b*SEQ*DK;
    const float* kh = g_kh + (size_t)b*SEQ*DK;
    const float* vh = g_vh + (size_t)b*SEQ*DK;
    const int tid = threadIdx.x;
    const int tx = tid & 15, ty = tid >> 4;

    for (int i = tid; i < 64*16; i += 256) {
        int r = i >> 4, c4 = (i & 15) << 2;
        float4 qv = *(const float4*)(qh + (size_t)(q0+r)*DK + c4);
        Qs[r][c4+0] = qv.x; Qs[r][c4+1] = qv.y;
        Qs[r][c4+2] = qv.z; Qs[r][c4+3] = qv.w;
    }
    if (tid < 64) { mrow[tid] = -1e30f; lrow[tid] = 0.f; }
    float o[4][4] = {};
    __syncthreads();

    for (int k0 = 0; k0 < SEQ; k0 += 64) {
        // load K/V tiles
        for (int i = tid; i < 64*16; i += 256) {
            int r = i >> 4, c4 = (i & 15) << 2;
            float4 kv = *(const float4*)(kh + (size_t)(k0+r)*DK + c4);
            Ks[r][c4+0] = kv.x; Ks[r][c4+1] = kv.y;
            Ks[r][c4+2] = kv.z; Ks[r][c4+3] = kv.w;
            float4 vv = *(const float4*)(vh + (size_t)(k0+r)*DK + c4);
            *(float4*)&Vs[r][c4] = vv;
        }
        __syncthreads();

        // scores (Q pre-scaled by 1/8 in projection)
        float s[4][4] = {};
        #pragma unroll
        for (int kk = 0; kk < 64; kk++) {
            float a[4], bb[4];
            #pragma unroll
            for (int i = 0; i < 4; i++) a[i] = Qs[ty*4+i][kk];
            #pragma unroll
            for (int j = 0; j < 4; j++) bb[j] = Ks[tx*4+j][kk];
            #pragma unroll
            for (int i = 0; i < 4; i++)
                #pragma unroll
                for (int j = 0; j < 4; j++)
                    s[i][j] += a[i]*bb[j];
        }
        // mask + stage scores in smem
        #pragma unroll
        for (int i = 0; i < 4; i++) {
            int qi = q0 + ty*4 + i;
            #pragma unroll
            for (int j = 0; j < 4; j++) {
                int kj = k0 + tx*4 + j;
                int mv = mask[(size_t)qi*SEQ + kj];
                Ps[ty*4+i][tx*4+j] = mv ? s[i][j] : -1e9f;
            }
        }
        __syncthreads();

        // online softmax update: 4 threads per row
        {
            int row = tid >> 2, sub = tid & 3;
            float mx = -1e30f;
            #pragma unroll 4
            for (int c = sub; c < 64; c += 4) mx = fmaxf(mx, Ps[row][c]);
            mx = fmaxf(mx, __shfl_xor_sync(0xffffffffu, mx, 1));
            mx = fmaxf(mx, __shfl_xor_sync(0xffffffffu, mx, 2));
            float mold = mrow[row];
            float mnew = fmaxf(mold, mx);
            float sum = 0.f;
            #pragma unroll 4
            for (int c = sub; c < 64; c += 4) {
                float p = __expf(Ps[row][c] - mnew);
                Ps[row][c] = p;
                sum += p;
            }
            sum += __shfl_xor_sync(0xffffffffu, sum, 1);
            sum += __shfl_xor_sync(0xffffffffu, sum, 2);
            if (sub == 0) {
                float corr = __expf(mold - mnew);
                crow[row] = corr;
                lrow[row] = lrow[row]*corr + sum;
                mrow[row] = mnew;
            }
        }
        __syncthreads();

        // O = O*corr + P @ V
        float cr[4];
        #pragma unroll
        for (int i = 0; i < 4; i++) cr[i] = crow[ty*4+i];
        #pragma unroll
        for (int i = 0; i < 4; i++)
            #pragma unroll
            for (int j = 0; j < 4; j++)
                o[i][j] *= cr[i];
        #pragma unroll
        for (int kk = 0; kk < 64; kk++) {
            float p[4];
            #pragma unroll
            for (int i = 0; i < 4; i++) p[i] = Ps[ty*4+i][kk];
            float4 vv = *(const float4*)&Vs[kk][tx*4];
            #pragma unroll
            for (int i = 0; i < 4; i++) {
                o[i][0] += p[i]*vv.x; o[i][1] += p[i]*vv.y;
                o[i][2] += p[i]*vv.z; o[i][3] += p[i]*vv.w;
            }
        }
        __syncthreads();
    }

    // normalize + store
    float* ao = g_ao + (size_t)b*SEQ*DK;
    #pragma unroll
    for (int i = 0; i < 4; i++) {
        float inv = 1.f / lrow[ty*4+i];
        float4 ov;
        ov.x = o[i][0]*inv; ov.y = o[i][1]*inv;
        ov.z = o[i][2]*inv; ov.w = o[i][3]*inv;
        *(float4*)(ao + (size_t)(q0 + ty*4 + i)*DK + tx*4) = ov;
    }
}

// ---------------------------------------------------------------------------
// Output projection: out[M,1024] = g_ao[M,64] @ Wo[1024,64]^T + bo
// ---------------------------------------------------------------------------
__global__ __launch_bounds__(256) void oproj_kernel(
    const float* __restrict__ Wo, const float* __restrict__ bo,
    float* __restrict__ out)
{
    __shared__ float As[64][65];
    __shared__ float Ws[64][65];
    const int row0 = blockIdx.x * 64;
    const int n0   = blockIdx.y * 64;
    const int tx = threadIdx.x & 15;
    const int ty = threadIdx.x >> 4;

    for (int i = threadIdx.x; i < 64*16; i += 256) {
        int r = i >> 4, c4 = (i & 15) << 2;
        float4 av = *(const float4*)(g_ao + (size_t)(row0 + r)*DK + c4);
        As[r][c4+0] = av.x; As[r][c4+1] = av.y;
        As[r][c4+2] = av.z; As[r][c4+3] = av.w;
        float4 wv = *(const float4*)(Wo + (size_t)(n0 + r)*DK + c4);
        Ws[r][c4+0] = wv.x; Ws[r][c4+1] = wv.y;
        Ws[r][c4+2] = wv.z; Ws[r][c4+3] = wv.w;
    }
    __syncthreads();

    float acc[4][4] = {};
    #pragma unroll
    for (int kk = 0; kk < 64; kk++) {
        float a[4], b[4];
        #pragma unroll
        for (int i = 0; i < 4; i++) a[i] = As[ty*4+i][kk];
        #pragma unroll
        for (int j = 0; j < 4; j++) b[j] = Ws[tx*4+j][kk];
        #pragma unroll
        for (int i = 0; i < 4; i++)
            #pragma unroll
            for (int j = 0; j < 4; j++)
                acc[i][j] += a[i]*b[j];
    }

    #pragma unroll
    for (int i = 0; i < 4; i++) {
        int r = row0 + ty*4 + i;
        float4 ov;
        ov.x = acc[i][0] + bo[n0 + tx*4 + 0];
        ov.y = acc[i][1] + bo[n0 + tx*4 + 1];
        ov.z = acc[i][2] + bo[n0 + tx*4 + 2];
        ov.w = acc[i][3] + bo[n0 + tx*4 + 3];
        *(float4*)(out + (size_t)r*DM + n0 + tx*4) = ov;
    }
}

// ---------------------------------------------------------------------------
extern "C" void kernel_launch(void* const* d_in, const int* in_sizes, int n_in,
                              void* d_out, int out_size)
{
    const float* q    = (const float*)d_in[0];
    const float* k    = (const float*)d_in[1];
    const float* v    = (const float*)d_in[2];
    const int*   mask = (const int*)  d_in[3];
    const float* Wq   = (const float*)d_in[4];
    const float* bq   = (const float*)d_in[5];
    const float* Wk   = (const float*)d_in[6];
    const float* bk   = (const float*)d_in[7];
    const float* Wv   = (const float*)d_in[8];
    const float* bv   = (const float*)d_in[9];
    const float* Wo   = (const float*)d_in[10];
    const float* bo   = (const float*)d_in[11];
    float* out = (float*)d_out;

    void *p_qh = nullptr, *p_kh = nullptr, *p_vh = nullptr;
    cudaGetSymbolAddress(&p_qh, g_qh);
    cudaGetSymbolAddress(&p_kh, g_kh);
    cudaGetSymbolAddress(&p_vh, g_vh);

    const int attn_smem = (2*64*65 + 64*68 + 64*65) * (int)sizeof(float);
    cudaFuncSetAttribute(attn_kernel,
                         cudaFuncAttributeMaxDynamicSharedMemorySize, attn_smem);

    const float qscale = 0.125f;  // 1/sqrt(64), folded into Q projection
    proj_kernel<<<MTOT/64, 256>>>(q, Wq, bq, (float*)p_qh, qscale);
    proj_kernel<<<MTOT/64, 256>>>(k, Wk, bk, (float*)p_kh, 1.0f);
    proj_kernel<<<MTOT/64, 256>>>(v, Wv, bv, (float*)p_vh, 1.0f);

    attn_kernel<<<dim3(SEQ/64, BB), 256, attn_smem>>>(mask);

    oproj_kernel<<<dim3(MTOT/64, DM/64), 256>>>(Wo, bo, out);
}

// round 3
// speedup vs baseline: 1.6270x; 1.6270x over previous
#include <cuda_runtime.h>
#include <cuda_bf16.h>
#include <stdint.h>

#define BB 4
#define SEQ 4096
#define DM 1024
#define DK 64
#define MTOT (BB*SEQ)

// ---------------------------------------------------------------------------
// Scratch (device globals — allocation-free)
// ---------------------------------------------------------------------------
__device__ float g_ao[MTOT*DK];                                  // attention out fp32
__device__ alignas(16) __nv_bfloat16 g_qh_hi[MTOT*DK];           // [b*S+s][dk]
__device__ alignas(16) __nv_bfloat16 g_qh_lo[MTOT*DK];
__device__ alignas(16) __nv_bfloat16 g_kh_hi[MTOT*DK];
__device__ alignas(16) __nv_bfloat16 g_kh_lo[MTOT*DK];
__device__ alignas(16) __nv_bfloat16 g_vt_hi[MTOT*DK];           // [b][dv][s]  (transposed)
__device__ alignas(16) __nv_bfloat16 g_vt_lo[MTOT*DK];
__device__ uint32_t g_mpack[SEQ*SEQ/32];                         // bit-packed mask

// ---------------------------------------------------------------------------
// helpers
// ---------------------------------------------------------------------------
__device__ __forceinline__ uint32_t smem_u32(const void* p) {
    uint32_t a;
    asm("{ .reg .u64 t; cvta.to.shared.u64 t, %1; cvt.u32.u64 %0, t; }"
        : "=r"(a) : "l"(p));
    return a;
}
__device__ __forceinline__ uint32_t pack_bf16(float a, float b) {
    __nv_bfloat162 h = __floats2bfloat162_rn(a, b);
    return *reinterpret_cast<uint32_t*>(&h);
}
__device__ __forceinline__ void split_bf16(float v, __nv_bfloat16& hi, __nv_bfloat16& lo) {
    hi = __float2bfloat16(v);
    lo = __float2bfloat16(v - __bfloat162float(hi));
}

#define LDSM_X4(r0,r1,r2,r3,addr) \
    asm volatile("ldmatrix.sync.aligned.m8n8.x4.shared.b16 {%0,%1,%2,%3}, [%4];" \
        : "=r"(r0), "=r"(r1), "=r"(r2), "=r"(r3) : "r"(addr))

#define MMA16816(c, a0,a1,a2,a3, b0,b1) \
    asm volatile("mma.sync.aligned.m16n8k16.row.col.f32.bf16.bf16.f32 " \
        "{%0,%1,%2,%3},{%4,%5,%6,%7},{%8,%9},{%0,%1,%2,%3};" \
        : "+f"((c)[0]), "+f"((c)[1]), "+f"((c)[2]), "+f"((c)[3]) \
        : "r"(a0), "r"(a1), "r"(a2), "r"(a3), "r"(b0), "r"(b1))

// ---------------------------------------------------------------------------
// mask bit-pack: one uint32 word per 32 mask ints (warp ballot)
// ---------------------------------------------------------------------------
__global__ __launch_bounds__(256) void pack_mask_kernel(const int* __restrict__ m)
{
    int w = blockIdx.x * 8 + (threadIdx.x >> 5);
    int lane = threadIdx.x & 31;
    int v = m[(size_t)w*32 + lane];
    uint32_t b = __ballot_sync(0xffffffffu, v != 0);
    if (lane == 0) g_mpack[w] = b;
}

// ---------------------------------------------------------------------------
// Q/K projection: y[M,64] = (x @ W^T + b)*prescale, emitted as bf16 hi/lo
// ---------------------------------------------------------------------------
__global__ __launch_bounds__(256) void proj_qk_kernel(
    const float* __restrict__ x, const float* __restrict__ W,
    const float* __restrict__ bias,
    __nv_bfloat16* __restrict__ yhi, __nv_bfloat16* __restrict__ ylo,
    float prescale)
{
    __shared__ float Xs[64][65];
    __shared__ float Ws[64][65];
    const int row0 = blockIdx.x * 64;
    const int tx = threadIdx.x & 15;
    const int ty = threadIdx.x >> 4;
    float acc[4][4] = {};

    for (int k0 = 0; k0 < DM; k0 += 64) {
        for (int i = threadIdx.x; i < 64*16; i += 256) {
            int r = i >> 4, c4 = (i & 15) << 2;
            float4 xv = *(const float4*)(x + (size_t)(row0 + r)*DM + k0 + c4);
            Xs[r][c4+0] = xv.x; Xs[r][c4+1] = xv.y; Xs[r][c4+2] = xv.z; Xs[r][c4+3] = xv.w;
            float4 wv = *(const float4*)(W + (size_t)r*DM + k0 + c4);
            Ws[r][c4+0] = wv.x; Ws[r][c4+1] = wv.y; Ws[r][c4+2] = wv.z; Ws[r][c4+3] = wv.w;
        }
        __syncthreads();
        #pragma unroll
        for (int kk = 0; kk < 64; kk++) {
            float a[4], b[4];
            #pragma unroll
            for (int i = 0; i < 4; i++) a[i] = Xs[ty*4+i][kk];
            #pragma unroll
            for (int j = 0; j < 4; j++) b[j] = Ws[tx*4+j][kk];
            #pragma unroll
            for (int i = 0; i < 4; i++)
                #pragma unroll
                for (int j = 0; j < 4; j++)
                    acc[i][j] += a[i]*b[j];
        }
        __syncthreads();
    }

    #pragma unroll
    for (int i = 0; i < 4; i++) {
        int r = row0 + ty*4 + i;
        float y[4];
        #pragma unroll
        for (int j = 0; j < 4; j++) y[j] = (acc[i][j] + bias[tx*4+j]) * prescale;
        __nv_bfloat16 h[4], l[4];
        #pragma unroll
        for (int j = 0; j < 4; j++) split_bf16(y[j], h[j], l[j]);
        uint2 uh, ul;
        uh.x = pack_bf16(__bfloat162float(h[0]), __bfloat162float(h[1]));
        uh.y = pack_bf16(__bfloat162float(h[2]), __bfloat162float(h[3]));
        ul.x = pack_bf16(__bfloat162float(l[0]), __bfloat162float(l[1]));
        ul.y = pack_bf16(__bfloat162float(l[2]), __bfloat162float(l[3]));
        ((uint2*)yhi)[(size_t)r*16 + tx] = uh;
        ((uint2*)ylo)[(size_t)r*16 + tx] = ul;
    }
}

// ---------------------------------------------------------------------------
// V projection: emits TRANSPOSED bf16 hi/lo: g_vt[b][dv][s]
// ---------------------------------------------------------------------------
__global__ __launch_bounds__(256) void proj_v_kernel(
    const float* __restrict__ x, const float* __restrict__ W,
    const float* __restrict__ bias)
{
    __shared__ float Xs[64][65];
    __shared__ float Ws[64][65];
    const int row0 = blockIdx.x * 64;
    const int tx = threadIdx.x & 15;
    const int ty = threadIdx.x >> 4;
    float acc[4][4] = {};

    for (int k0 = 0; k0 < DM; k0 += 64) {
        for (int i = threadIdx.x; i < 64*16; i += 256) {
            int r = i >> 4, c4 = (i & 15) << 2;
            float4 xv = *(const float4*)(x + (size_t)(row0 + r)*DM + k0 + c4);
            Xs[r][c4+0] = xv.x; Xs[r][c4+1] = xv.y; Xs[r][c4+2] = xv.z; Xs[r][c4+3] = xv.w;
            float4 wv = *(const float4*)(W + (size_t)r*DM + k0 + c4);
            Ws[r][c4+0] = wv.x; Ws[r][c4+1] = wv.y; Ws[r][c4+2] = wv.z; Ws[r][c4+3] = wv.w;
        }
        __syncthreads();
        #pragma unroll
        for (int kk = 0; kk < 64; kk++) {
            float a[4], b[4];
            #pragma unroll
            for (int i = 0; i < 4; i++) a[i] = Xs[ty*4+i][kk];
            #pragma unroll
            for (int j = 0; j < 4; j++) b[j] = Ws[tx*4+j][kk];
            #pragma unroll
            for (int i = 0; i < 4; i++)
                #pragma unroll
                for (int j = 0; j < 4; j++)
                    acc[i][j] += a[i]*b[j];
        }
        __syncthreads();
    }

    const int b = row0 >> 12;
    const int sl0 = row0 & (SEQ-1);
    const size_t vbase = (size_t)b * DK * SEQ;
    #pragma unroll
    for (int i = 0; i < 4; i++) {
        int s = sl0 + ty*4 + i;
        #pragma unroll
        for (int j = 0; j < 4; j++) {
            int dv = tx*4 + j;
            float y = acc[i][j] + bias[dv];
            __nv_bfloat16 h, l;
            split_bf16(y, h, l);
            g_vt_hi[vbase + (size_t)dv*SEQ + s] = h;
            g_vt_lo[vbase + (size_t)dv*SEQ + s] = l;
        }
    }
}

// ---------------------------------------------------------------------------
// Flash attention via mma.sync (bf16x3). CTA = 128 q x 256 thr (8 warps x 16 rows).
// smem buffer (36864 B) holds Q hi/lo during prologue, then K/V hi/lo tiles.
// Row stride 72 bf16 (144 B) -> conflict-free ldmatrix.
// ---------------------------------------------------------------------------
#define RSTRIDE 72           // bf16 elements per smem row
#define RSTRIDE_B 144

__global__ __launch_bounds__(256, 1) void attn_mma_kernel()
{
    __shared__ alignas(16) __nv_bfloat16 sbuf[128*RSTRIDE*2];  // 36864 B

    const int tid = threadIdx.x;
    const int w   = tid >> 5;          // warp 0..7
    const int l   = tid & 31;          // lane
    const int b   = blockIdx.y;
    const int q0  = blockIdx.x * 128;

    const uint32_t sbase = smem_u32(sbuf);

    // ---------------- Q fragments (once) ----------------
    // stage Q hi (rows 0..127) at sbuf, Q lo at sbuf + 128*RSTRIDE
    {
        const uint4* gqh = (const uint4*)(g_qh_hi + (size_t)(b*SEQ + q0)*DK);
        const uint4* gql = (const uint4*)(g_qh_lo + (size_t)(b*SEQ + q0)*DK);
        #pragma unroll
        for (int it = 0; it < 4; it++) {
            int i = tid + it*256;            // 0..1023
            int r = i >> 3, c = i & 7;
            *(uint4*)((char*)sbuf + r*RSTRIDE_B + c*16) = gqh[i];
            *(uint4*)((char*)sbuf + 128*RSTRIDE_B + r*RSTRIDE_B + c*16) = gql[i];
        }
    }
    __syncthreads();

    uint32_t qa_h[4][4], qa_l[4][4];
    {
        // A-frag ldmatrix addressing: row = m0 + (l%8) + ((l/8)&1)*8 ; colb = t*32 + ((l/8)&2)*8
        int row = w*16 + (l & 7) + ((l >> 3) & 1)*8;
        int colb_off = ((l >> 3) & 2)*8;
        #pragma unroll
        for (int t = 0; t < 4; t++) {
            uint32_t a = sbase + row*RSTRIDE_B + t*32 + colb_off;
            LDSM_X4(qa_h[t][0], qa_h[t][1], qa_h[t][2], qa_h[t][3], a);
            LDSM_X4(qa_l[t][0], qa_l[t][1], qa_l[t][2], qa_l[t][3],
                    a + 128*RSTRIDE_B);
        }
    }
    __syncthreads();

    // smem carve for main loop (byte offsets)
    const uint32_t oKh = 0;
    const uint32_t oKl = 64*RSTRIDE_B;
    const uint32_t oVh = 128*RSTRIDE_B;
    const uint32_t oVl = 192*RSTRIDE_B;

    // B-frag ldmatrix addressing pieces
    const int brow_off = (l & 7) + ((l >> 3) & 2)*4;     // within n16 group
    const int bcol_off = ((l >> 3) & 1)*16;              // bytes

    // O accumulators: 8 n-frags x 4 (rows lo/lo, hi/hi pattern of C layout)
    float O[8][4];
    #pragma unroll
    for (int j = 0; j < 8; j++)
        #pragma unroll
        for (int i = 0; i < 4; i++) O[j][i] = 0.f;
    float mr[2] = {-1e30f, -1e30f};
    float lr[2] = {0.f, 0.f};

    const int q_lo = q0 + w*16 + (l >> 2);
    const int q_hi = q_lo + 8;

    const uint4* gkh = (const uint4*)(g_kh_hi + (size_t)b*SEQ*DK);
    const uint4* gkl = (const uint4*)(g_kh_lo + (size_t)b*SEQ*DK);
    const uint4* gvh = (const uint4*)(g_vt_hi + (size_t)b*DK*SEQ);
    const uint4* gvl = (const uint4*)(g_vt_lo + (size_t)b*DK*SEQ);

    for (int k0 = 0; k0 < SEQ; k0 += 64) {
        // ------------ stage K (rows=key) and V^T (rows=dv) tiles ------------
        #pragma unroll
        for (int it = 0; it < 2; it++) {
            int i = tid + it*256;            // 0..511
            int r = i >> 3, c = i & 7;
            uint32_t d = r*RSTRIDE_B + c*16;
            *(uint4*)((char*)sbuf + oKh + d) = gkh[(size_t)(k0 + r)*8 + c];
            *(uint4*)((char*)sbuf + oKl + d) = gkl[(size_t)(k0 + r)*8 + c];
            int vi = r*(SEQ/8) + (k0 >> 3) + c;
            *(uint4*)((char*)sbuf + oVh + d) = gvh[vi];
            *(uint4*)((char*)sbuf + oVl + d) = gvl[vi];
        }
        __syncthreads();

        // ------------ S = Q K^T  (bf16x3) ------------
        float S[8][4];
        #pragma unroll
        for (int j = 0; j < 8; j++)
            #pragma unroll
            for (int i = 0; i < 4; i++) S[j][i] = 0.f;

        #pragma unroll
        for (int t = 0; t < 4; t++) {
            #pragma unroll
            for (int g = 0; g < 4; g++) {
                uint32_t a = sbase + (g*16 + brow_off)*RSTRIDE_B + t*32 + bcol_off;
                uint32_t h0,h1,h2,h3, l0,l1,l2,l3;
                LDSM_X4(h0,h1,h2,h3, a + oKh);
                LDSM_X4(l0,l1,l2,l3, a + oKl);
                MMA16816(S[2*g],   qa_h[t][0],qa_h[t][1],qa_h[t][2],qa_h[t][3], h0,h1);
                MMA16816(S[2*g],   qa_h[t][0],qa_h[t][1],qa_h[t][2],qa_h[t][3], l0,l1);
                MMA16816(S[2*g],   qa_l[t][0],qa_l[t][1],qa_l[t][2],qa_l[t][3], h0,h1);
                MMA16816(S[2*g+1], qa_h[t][0],qa_h[t][1],qa_h[t][2],qa_h[t][3], h2,h3);
                MMA16816(S[2*g+1], qa_h[t][0],qa_h[t][1],qa_h[t][2],qa_h[t][3], l2,l3);
                MMA16816(S[2*g+1], qa_l[t][0],qa_l[t][1],qa_l[t][2],qa_l[t][3], h2,h3);
            }
        }

        // ------------ mask ------------
        {
            uint2 m0 = *(const uint2*)(g_mpack + (size_t)q_lo*(SEQ/32) + (k0 >> 5));
            uint2 m1 = *(const uint2*)(g_mpack + (size_t)q_hi*(SEQ/32) + (k0 >> 5));
            uint64_t w0 = ((uint64_t)m0.y << 32) | m0.x;
            uint64_t w1 = ((uint64_t)m1.y << 32) | m1.x;
            #pragma unroll
            for (int j = 0; j < 8; j++) {
                int c = j*8 + 2*(l & 3);
                if (!((w0 >> c) & 1))     S[j][0] = -1e9f;
                if (!((w0 >> (c+1)) & 1)) S[j][1] = -1e9f;
                if (!((w1 >> c) & 1))     S[j][2] = -1e9f;
                if (!((w1 >> (c+1)) & 1)) S[j][3] = -1e9f;
            }
        }

        // ------------ online softmax ------------
        float mx0 = -1e30f, mx1 = -1e30f;
        #pragma unroll
        for (int j = 0; j < 8; j++) {
            mx0 = fmaxf(mx0, fmaxf(S[j][0], S[j][1]));
            mx1 = fmaxf(mx1, fmaxf(S[j][2], S[j][3]));
        }
        mx0 = fmaxf(mx0, __shfl_xor_sync(0xffffffffu, mx0, 1));
        mx0 = fmaxf(mx0, __shfl_xor_sync(0xffffffffu, mx0, 2));
        mx1 = fmaxf(mx1, __shfl_xor_sync(0xffffffffu, mx1, 1));
        mx1 = fmaxf(mx1, __shfl_xor_sync(0xffffffffu, mx1, 2));
        float mn0 = fmaxf(mr[0], mx0), mn1 = fmaxf(mr[1], mx1);
        float cr0 = __expf(mr[0] - mn0), cr1 = __expf(mr[1] - mn1);
        mr[0] = mn0; mr[1] = mn1;

        float ps0 = 0.f, ps1 = 0.f;
        uint32_t pa_h[4][4], pa_l[4][4];
        #pragma unroll
        for (int t = 0; t < 4; t++) {
            float p[8];
            #pragma unroll
            for (int u = 0; u < 2; u++) {
                int j = 2*t + u;
                p[4*u+0] = __expf(S[j][0] - mn0);
                p[4*u+1] = __expf(S[j][1] - mn0);
                p[4*u+2] = __expf(S[j][2] - mn1);
                p[4*u+3] = __expf(S[j][3] - mn1);
                ps0 += p[4*u+0] + p[4*u+1];
                ps1 += p[4*u+2] + p[4*u+3];
            }
            // pack A-frags: Ra0=(rowlo,klo) Ra1=(rowhi,klo) Ra2=(rowlo,khi) Ra3=(rowhi,khi)
            float h00,h01,h02,h03,h04,h05,h06,h07;
            #pragma unroll
            for (int u = 0; u < 1; u++) {}  // (no-op, keep scope)
            __nv_bfloat16 bh, bl;
            float lo[8];
            #pragma unroll
            for (int e = 0; e < 8; e++) {
                split_bf16(p[e], bh, bl);
                p[e]  = __bfloat162float(bh);
                lo[e] = __bfloat162float(bl);
            }
            pa_h[t][0] = pack_bf16(p[0], p[1]);
            pa_h[t][1] = pack_bf16(p[2], p[3]);
            pa_h[t][2] = pack_bf16(p[4], p[5]);
            pa_h[t][3] = pack_bf16(p[6], p[7]);
            pa_l[t][0] = pack_bf16(lo[0], lo[1]);
            pa_l[t][1] = pack_bf16(lo[2], lo[3]);
            pa_l[t][2] = pack_bf16(lo[4], lo[5]);
            pa_l[t][3] = pack_bf16(lo[6], lo[7]);
            (void)h00;(void)h01;(void)h02;(void)h03;(void)h04;(void)h05;(void)h06;(void)h07;
        }
        ps0 += __shfl_xor_sync(0xffffffffu, ps0, 1);
        ps0 += __shfl_xor_sync(0xffffffffu, ps0, 2);
        ps1 += __shfl_xor_sync(0xffffffffu, ps1, 1);
        ps1 += __shfl_xor_sync(0xffffffffu, ps1, 2);
        lr[0] = lr[0]*cr0 + ps0;
        lr[1] = lr[1]*cr1 + ps1;

        // rescale O
        #pragma unroll
        for (int j = 0; j < 8; j++) {
            O[j][0] *= cr0; O[j][1] *= cr0;
            O[j][2] *= cr1; O[j][3] *= cr1;
        }

        // ------------ O += P V  (bf16x3) ------------
        #pragma unroll
        for (int t = 0; t < 4; t++) {
            #pragma unroll
            for (int g = 0; g < 4; g++) {
                uint32_t a = sbase + (g*16 + brow_off)*RSTRIDE_B + t*32 + bcol_off;
                uint32_t h0,h1,h2,h3, l0,l1,l2,l3;
                LDSM_X4(h0,h1,h2,h3, a + oVh);
                LDSM_X4(l0,l1,l2,l3, a + oVl);
                MMA16816(O[2*g],   pa_h[t][0],pa_h[t][1],pa_h[t][2],pa_h[t][3], h0,h1);
                MMA16816(O[2*g],   pa_h[t][0],pa_h[t][1],pa_h[t][2],pa_h[t][3], l0,l1);
                MMA16816(O[2*g],   pa_l[t][0],pa_l[t][1],pa_l[t][2],pa_l[t][3], h0,h1);
                MMA16816(O[2*g+1], pa_h[t][0],pa_h[t][1],pa_h[t][2],pa_h[t][3], h2,h3);
                MMA16816(O[2*g+1], pa_h[t][0],pa_h[t][1],pa_h[t][2],pa_h[t][3], l2,l3);
                MMA16816(O[2*g+1], pa_l[t][0],pa_l[t][1],pa_l[t][2],pa_l[t][3], h2,h3);
            }
        }
        __syncthreads();
    }

    // ------------ normalize + store ------------
    {
        float inv0 = 1.f / lr[0];
        float inv1 = 1.f / lr[1];
        float* ao0 = g_ao + (size_t)(b*SEQ + q_lo)*DK;
        float* ao1 = g_ao + (size_t)(b*SEQ + q_hi)*DK;
        #pragma unroll
        for (int j = 0; j < 8; j++) {
            int c = j*8 + 2*(l & 3);
            float2 v0 = { O[j][0]*inv0, O[j][1]*inv0 };
            float2 v1 = { O[j][2]*inv1, O[j][3]*inv1 };
            *(float2*)(ao0 + c) = v0;
            *(float2*)(ao1 + c) = v1;
        }
    }
}

// ---------------------------------------------------------------------------
// Output projection: out[M,1024] = g_ao[M,64] @ Wo[1024,64]^T + bo
// ---------------------------------------------------------------------------
__global__ __launch_bounds__(256) void oproj_kernel(
    const float* __restrict__ Wo, const float* __restrict__ bo,
    float* __restrict__ out)
{
    __shared__ float As[64][65];
    __shared__ float Ws[64][65];
    const int row0 = blockIdx.x * 64;
    const int n0   = blockIdx.y * 64;
    const int tx = threadIdx.x & 15;
    const int ty = threadIdx.x >> 4;

    for (int i = threadIdx.x; i < 64*16; i += 256) {
        int r = i >> 4, c4 = (i & 15) << 2;
        float4 av = *(const float4*)(g_ao + (size_t)(row0 + r)*DK + c4);
        As[r][c4+0] = av.x; As[r][c4+1] = av.y; As[r][c4+2] = av.z; As[r][c4+3] = av.w;
        float4 wv = *(const float4*)(Wo + (size_t)(n0 + r)*DK + c4);
        Ws[r][c4+0] = wv.x; Ws[r][c4+1] = wv.y; Ws[r][c4+2] = wv.z; Ws[r][c4+3] = wv.w;
    }
    __syncthreads();

    float acc[4][4] = {};
    #pragma unroll
    for (int kk = 0; kk < 64; kk++) {
        float a[4], b[4];
        #pragma unroll
        for (int i = 0; i < 4; i++) a[i] = As[ty*4+i][kk];
        #pragma unroll
        for (int j = 0; j < 4; j++) b[j] = Ws[tx*4+j][kk];
        #pragma unroll
        for (int i = 0; i < 4; i++)
            #pragma unroll
            for (int j = 0; j < 4; j++)
                acc[i][j] += a[i]*b[j];
    }

    #pragma unroll
    for (int i = 0; i < 4; i++) {
        int r = row0 + ty*4 + i;
        float4 ov;
        ov.x = acc[i][0] + bo[n0 + tx*4 + 0];
        ov.y = acc[i][1] + bo[n0 + tx*4 + 1];
        ov.z = acc[i][2] + bo[n0 + tx*4 + 2];
        ov.w = acc[i][3] + bo[n0 + tx*4 + 3];
        *(float4*)(out + (size_t)r*DM + n0 + tx*4) = ov;
    }
}

// ---------------------------------------------------------------------------
extern "C" void kernel_launch(void* const* d_in, const int* in_sizes, int n_in,
                              void* d_out, int out_size)
{
    const float* q    = (const float*)d_in[0];
    const float* k    = (const float*)d_in[1];
    const float* v    = (const float*)d_in[2];
    const int*   mask = (const int*)  d_in[3];
    const float* Wq   = (const float*)d_in[4];
    const float* bq   = (const float*)d_in[5];
    const float* Wk   = (const float*)d_in[6];
    const float* bk   = (const float*)d_in[7];
    const float* Wv   = (const float*)d_in[8];
    const float* bv   = (const float*)d_in[9];
    const float* Wo   = (const float*)d_in[10];
    const float* bo   = (const float*)d_in[11];
    float* out = (float*)d_out;

    void *p_qh_hi=nullptr, *p_qh_lo=nullptr, *p_kh_hi=nullptr, *p_kh_lo=nullptr;
    cudaGetSymbolAddress(&p_qh_hi, g_qh_hi);
    cudaGetSymbolAddress(&p_qh_lo, g_qh_lo);
    cudaGetSymbolAddress(&p_kh_hi, g_kh_hi);
    cudaGetSymbolAddress(&p_kh_lo, g_kh_lo);

    pack_mask_kernel<<<SEQ*SEQ/32/8, 256>>>(mask);

    const float qscale = 0.125f;  // 1/sqrt(64), exact power of 2
    proj_qk_kernel<<<MTOT/64, 256>>>(q, Wq, bq,
        (__nv_bfloat16*)p_qh_hi, (__nv_bfloat16*)p_qh_lo, qscale);
    proj_qk_kernel<<<MTOT/64, 256>>>(k, Wk, bk,
        (__nv_bfloat16*)p_kh_hi, (__nv_bfloat16*)p_kh_lo, 1.0f);
    proj_v_kernel<<<MTOT/64, 256>>>(v, Wv, bv);

    attn_mma_kernel<<<dim3(SEQ/128, BB), 256>>>();

    oproj_kernel<<<dim3(MTOT/64, DM/64), 256>>>(Wo, bo, out);
}

// round 4
// speedup vs baseline: 2.4696x; 1.5179x over previous
#include <cuda_runtime.h>
#include <cuda_bf16.h>
#include <stdint.h>

#define BB 4
#define SEQ 4096
#define DM 1024
#define DK 64
#define MTOT (BB*SEQ)

#define RSTRIDE_B 144      // smem row stride in bytes (64 bf16 + 8 pad)

// ---------------------------------------------------------------------------
// Scratch (device globals — allocation-free)
// ---------------------------------------------------------------------------
__device__ alignas(16) __nv_bfloat16 g_qh_hi[MTOT*DK];   // [b*S+s][dk]
__device__ alignas(16) __nv_bfloat16 g_qh_lo[MTOT*DK];
__device__ alignas(16) __nv_bfloat16 g_kh_hi[MTOT*DK];
__device__ alignas(16) __nv_bfloat16 g_kh_lo[MTOT*DK];
__device__ alignas(16) __nv_bfloat16 g_vh_hi[MTOT*DK];   // row-major [b*S+s][dv]
__device__ alignas(16) __nv_bfloat16 g_vh_lo[MTOT*DK];
__device__ alignas(16) __nv_bfloat16 g_aoh[MTOT*DK];     // attn out hi
__device__ alignas(16) __nv_bfloat16 g_aol[MTOT*DK];     // attn out lo
__device__ uint32_t g_mpack[SEQ*SEQ/32];                 // bit-packed mask

// ---------------------------------------------------------------------------
// helpers
// ---------------------------------------------------------------------------
__device__ __forceinline__ uint32_t smem_u32(const void* p) {
    uint32_t a;
    asm("{ .reg .u64 t; cvta.to.shared.u64 t, %1; cvt.u32.u64 %0, t; }"
        : "=r"(a) : "l"(p));
    return a;
}
__device__ __forceinline__ uint32_t pack_bf16(float a, float b) {
    __nv_bfloat162 h = __floats2bfloat162_rn(a, b);
    return *reinterpret_cast<uint32_t*>(&h);
}
__device__ __forceinline__ void split_bf16(float v, float& hi, float& lo) {
    __nv_bfloat16 h = __float2bfloat16(v);
    hi = __bfloat162float(h);
    lo = v - hi;
}

#define LDSM_X4(r0,r1,r2,r3,addr) \
    asm volatile("ldmatrix.sync.aligned.m8n8.x4.shared.b16 {%0,%1,%2,%3}, [%4];" \
        : "=r"(r0), "=r"(r1), "=r"(r2), "=r"(r3) : "r"(addr))

#define LDSM_X4_T(r0,r1,r2,r3,addr) \
    asm volatile("ldmatrix.sync.aligned.m8n8.x4.trans.shared.b16 {%0,%1,%2,%3}, [%4];" \
        : "=r"(r0), "=r"(r1), "=r"(r2), "=r"(r3) : "r"(addr))

#define MMA16816(c, a0,a1,a2,a3, b0,b1) \
    asm volatile("mma.sync.aligned.m16n8k16.row.col.f32.bf16.bf16.f32 " \
        "{%0,%1,%2,%3},{%4,%5,%6,%7},{%8,%9},{%0,%1,%2,%3};" \
        : "+f"((c)[0]), "+f"((c)[1]), "+f"((c)[2]), "+f"((c)[3]) \
        : "r"(a0), "r"(a1), "r"(a2), "r"(a3), "r"(b0), "r"(b1))

// ---------------------------------------------------------------------------
// mask bit-pack
// ---------------------------------------------------------------------------
__global__ __launch_bounds__(256) void pack_mask_kernel(const int* __restrict__ m)
{
    int w = blockIdx.x * 8 + (threadIdx.x >> 5);
    int lane = threadIdx.x & 31;
    int v = m[(size_t)w*32 + lane];
    uint32_t b = __ballot_sync(0xffffffffu, v != 0);
    if (lane == 0) g_mpack[w] = b;
}

// ---------------------------------------------------------------------------
// Q/K/V projection on tensor cores (bf16x3).
// CTA: 128 rows x 64 out-dims; grid (MTOT/128, 3) -> z selects q/k/v.
// smem: sXh(128x72) sXl sWh(64x72) sWl  = 55296 B dynamic
// ---------------------------------------------------------------------------
__global__ __launch_bounds__(256, 1) void proj_mma_kernel(
    const float* __restrict__ q, const float* __restrict__ k, const float* __restrict__ v,
    const float* __restrict__ Wq, const float* __restrict__ Wk, const float* __restrict__ Wv,
    const float* __restrict__ bq, const float* __restrict__ bk, const float* __restrict__ bv)
{
    extern __shared__ char psm[];
    char* sXh = psm;                          // 128*144
    char* sXl = psm + 128*RSTRIDE_B;          // 128*144
    char* sWh = psm + 256*RSTRIDE_B;          // 64*144
    char* sWl = psm + 320*RSTRIDE_B;          // 64*144

    const int tid = threadIdx.x;
    const int w = tid >> 5, l = tid & 31;
    const int z = blockIdx.y;
    const int row0 = blockIdx.x * 128;

    const float* x    = (z == 0) ? q  : (z == 1) ? k  : v;
    const float* W    = (z == 0) ? Wq : (z == 1) ? Wk : Wv;
    const float* bias = (z == 0) ? bq : (z == 1) ? bk : bv;
    __nv_bfloat16* yh = (z == 0) ? g_qh_hi : (z == 1) ? g_kh_hi : g_vh_hi;
    __nv_bfloat16* yl = (z == 0) ? g_qh_lo : (z == 1) ? g_kh_lo : g_vh_lo;
    const float presc = (z == 0) ? 0.125f : 1.0f;

    const uint32_t aXh = smem_u32(sXh), aXl = smem_u32(sXl);
    const uint32_t aWh = smem_u32(sWh), aWl = smem_u32(sWl);

    const int arow  = w*16 + (l & 7) + ((l >> 3) & 1)*8;
    const int acolb = ((l >> 3) & 2)*8;
    const int brow  = (l & 7) + ((l >> 3) & 2)*4;
    const int bcolb = ((l >> 3) & 1)*16;

    float C[8][4];
    #pragma unroll
    for (int j = 0; j < 8; j++)
        #pragma unroll
        for (int i = 0; i < 4; i++) C[j][i] = 0.f;

    for (int k0 = 0; k0 < DM; k0 += 64) {
        // stage x chunk (fp32 -> bf16 hi/lo)
        #pragma unroll
        for (int it = 0; it < 8; it++) {
            int i = tid + it*256;            // 0..2047: 128 rows x 16 float4
            int r = i >> 4, c = i & 15;
            float4 xv = *(const float4*)(x + (size_t)(row0 + r)*DM + k0 + c*4);
            float h0,l0,h1,l1,h2,l2,h3,l3;
            split_bf16(xv.x, h0, l0); split_bf16(xv.y, h1, l1);
            split_bf16(xv.z, h2, l2); split_bf16(xv.w, h3, l3);
            uint2 uh = { pack_bf16(h0,h1), pack_bf16(h2,h3) };
            uint2 ul = { pack_bf16(l0,l1), pack_bf16(l2,l3) };
            *(uint2*)(sXh + r*RSTRIDE_B + c*8) = uh;
            *(uint2*)(sXl + r*RSTRIDE_B + c*8) = ul;
        }
        // stage W chunk (fp32 -> bf16 hi/lo): 64 rows x 16 float4
        #pragma unroll
        for (int it = 0; it < 4; it++) {
            int i = tid + it*256;            // 0..1023
            int r = i >> 4, c = i & 15;
            float4 wv = *(const float4*)(W + (size_t)r*DM + k0 + c*4);
            float h0,l0,h1,l1,h2,l2,h3,l3;
            split_bf16(wv.x, h0, l0); split_bf16(wv.y, h1, l1);
            split_bf16(wv.z, h2, l2); split_bf16(wv.w, h3, l3);
            uint2 uh = { pack_bf16(h0,h1), pack_bf16(h2,h3) };
            uint2 ul = { pack_bf16(l0,l1), pack_bf16(l2,l3) };
            *(uint2*)(sWh + r*RSTRIDE_B + c*8) = uh;
            *(uint2*)(sWl + r*RSTRIDE_B + c*8) = ul;
        }
        __syncthreads();

        #pragma unroll
        for (int t = 0; t < 4; t++) {
            uint32_t ah[4], al[4];
            uint32_t aa = aXh + arow*RSTRIDE_B + t*32 + acolb;
            LDSM_X4(ah[0], ah[1], ah[2], ah[3], aa);
            LDSM_X4(al[0], al[1], al[2], al[3], aa + (aXl - aXh));
            #pragma unroll
            for (int g = 0; g < 4; g++) {
                uint32_t ba = aWh + (g*16 + brow)*RSTRIDE_B + t*32 + bcolb;
                uint32_t h0,h1,h2,h3, w0,w1,w2,w3;
                LDSM_X4(h0,h1,h2,h3, ba);
                LDSM_X4(w0,w1,w2,w3, ba + (aWl - aWh));
                MMA16816(C[2*g],   ah[0],ah[1],ah[2],ah[3], h0,h1);
                MMA16816(C[2*g],   ah[0],ah[1],ah[2],ah[3], w0,w1);
                MMA16816(C[2*g],   al[0],al[1],al[2],al[3], h0,h1);
                MMA16816(C[2*g+1], ah[0],ah[1],ah[2],ah[3], h2,h3);
                MMA16816(C[2*g+1], ah[0],ah[1],ah[2],ah[3], w2,w3);
                MMA16816(C[2*g+1], al[0],al[1],al[2],al[3], h2,h3);
            }
        }
        __syncthreads();
    }

    // epilogue: +bias, *prescale, split bf16, store
    const int row_lo = row0 + w*16 + (l >> 2);
    const int row_hi = row_lo + 8;
    uint32_t* yh0 = (uint32_t*)(yh + (size_t)row_lo*DK);
    uint32_t* yl0 = (uint32_t*)(yl + (size_t)row_lo*DK);
    uint32_t* yh1 = (uint32_t*)(yh + (size_t)row_hi*DK);
    uint32_t* yl1 = (uint32_t*)(yl + (size_t)row_hi*DK);
    #pragma unroll
    for (int j = 0; j < 8; j++) {
        int c = j*8 + 2*(l & 3);
        float b0 = bias[c], b1 = bias[c+1];
        float v0 = (C[j][0] + b0)*presc, v1 = (C[j][1] + b1)*presc;
        float v2 = (C[j][2] + b0)*presc, v3 = (C[j][3] + b1)*presc;
        float h,lo0,h1f,lo1;
        split_bf16(v0, h, lo0); split_bf16(v1, h1f, lo1);
        yh0[j*4 + (l & 3)] = pack_bf16(h, h1f);
        yl0[j*4 + (l & 3)] = pack_bf16(lo0, lo1);
        split_bf16(v2, h, lo0); split_bf16(v3, h1f, lo1);
        yh1[j*4 + (l & 3)] = pack_bf16(h, h1f);
        yl1[j*4 + (l & 3)] = pack_bf16(lo0, lo1);
    }
}

// ---------------------------------------------------------------------------
// Flash attention via mma.sync (bf16x3). CTA = 128 q x 256 thr.
// V consumed row-major via ldmatrix.trans. Output bf16 hi/lo.
// ---------------------------------------------------------------------------
__global__ __launch_bounds__(256, 1) void attn_mma_kernel()
{
    __shared__ alignas(16) __nv_bfloat16 sbuf[128*72*2];  // 36864 B

    const int tid = threadIdx.x;
    const int w   = tid >> 5;
    const int l   = tid & 31;
    const int b   = blockIdx.y;
    const int q0  = blockIdx.x * 128;

    const uint32_t sbase = smem_u32(sbuf);

    // ---------------- Q fragments (once) ----------------
    {
        const uint4* gqh = (const uint4*)(g_qh_hi + (size_t)(b*SEQ + q0)*DK);
        const uint4* gql = (const uint4*)(g_qh_lo + (size_t)(b*SEQ + q0)*DK);
        #pragma unroll
        for (int it = 0; it < 4; it++) {
            int i = tid + it*256;
            int r = i >> 3, c = i & 7;
            *(uint4*)((char*)sbuf + r*RSTRIDE_B + c*16) = gqh[i];
            *(uint4*)((char*)sbuf + 128*RSTRIDE_B + r*RSTRIDE_B + c*16) = gql[i];
        }
    }
    __syncthreads();

    uint32_t qa_h[4][4], qa_l[4][4];
    {
        int row = w*16 + (l & 7) + ((l >> 3) & 1)*8;
        int colb_off = ((l >> 3) & 2)*8;
        #pragma unroll
        for (int t = 0; t < 4; t++) {
            uint32_t a = sbase + row*RSTRIDE_B + t*32 + colb_off;
            LDSM_X4(qa_h[t][0], qa_h[t][1], qa_h[t][2], qa_h[t][3], a);
            LDSM_X4(qa_l[t][0], qa_l[t][1], qa_l[t][2], qa_l[t][3],
                    a + 128*RSTRIDE_B);
        }
    }
    __syncthreads();

    const uint32_t oKh = 0;
    const uint32_t oKl = 64*RSTRIDE_B;
    const uint32_t oVh = 128*RSTRIDE_B;
    const uint32_t oVl = 192*RSTRIDE_B;

    const int brow_off = (l & 7) + ((l >> 3) & 2)*4;
    const int bcol_off = ((l >> 3) & 1)*16;
    // trans (V) addressing pieces
    const int vrow_off = (l & 7) + ((l >> 3) & 1)*8;
    const int vcol_off = ((l >> 4) & 1)*16;   // bytes (8 bf16)

    float O[8][4];
    #pragma unroll
    for (int j = 0; j < 8; j++)
        #pragma unroll
        for (int i = 0; i < 4; i++) O[j][i] = 0.f;
    float mr[2] = {-1e30f, -1e30f};
    float lr[2] = {0.f, 0.f};

    const int q_lo = q0 + w*16 + (l >> 2);
    const int q_hi = q_lo + 8;

    const uint4* gkh = (const uint4*)(g_kh_hi + (size_t)b*SEQ*DK);
    const uint4* gkl = (const uint4*)(g_kh_lo + (size_t)b*SEQ*DK);
    const uint4* gvh = (const uint4*)(g_vh_hi + (size_t)b*SEQ*DK);
    const uint4* gvl = (const uint4*)(g_vh_lo + (size_t)b*SEQ*DK);

    for (int k0 = 0; k0 < SEQ; k0 += 64) {
        // stage K and V tiles (both row-major [key][dk])
        #pragma unroll
        for (int it = 0; it < 2; it++) {
            int i = tid + it*256;
            int r = i >> 3, c = i & 7;
            uint32_t d = r*RSTRIDE_B + c*16;
            size_t gi = (size_t)(k0 + r)*8 + c;
            *(uint4*)((char*)sbuf + oKh + d) = gkh[gi];
            *(uint4*)((char*)sbuf + oKl + d) = gkl[gi];
            *(uint4*)((char*)sbuf + oVh + d) = gvh[gi];
            *(uint4*)((char*)sbuf + oVl + d) = gvl[gi];
        }
        __syncthreads();

        // ---- S = Q K^T ----
        float S[8][4];
        #pragma unroll
        for (int j = 0; j < 8; j++)
            #pragma unroll
            for (int i = 0; i < 4; i++) S[j][i] = 0.f;

        #pragma unroll
        for (int t = 0; t < 4; t++) {
            #pragma unroll
            for (int g = 0; g < 4; g++) {
                uint32_t a = sbase + (g*16 + brow_off)*RSTRIDE_B + t*32 + bcol_off;
                uint32_t h0,h1,h2,h3, l0,l1,l2,l3;
                LDSM_X4(h0,h1,h2,h3, a + oKh);
                LDSM_X4(l0,l1,l2,l3, a + oKl);
                MMA16816(S[2*g],   qa_h[t][0],qa_h[t][1],qa_h[t][2],qa_h[t][3], h0,h1);
                MMA16816(S[2*g],   qa_h[t][0],qa_h[t][1],qa_h[t][2],qa_h[t][3], l0,l1);
                MMA16816(S[2*g],   qa_l[t][0],qa_l[t][1],qa_l[t][2],qa_l[t][3], h0,h1);
                MMA16816(S[2*g+1], qa_h[t][0],qa_h[t][1],qa_h[t][2],qa_h[t][3], h2,h3);
                MMA16816(S[2*g+1], qa_h[t][0],qa_h[t][1],qa_h[t][2],qa_h[t][3], l2,l3);
                MMA16816(S[2*g+1], qa_l[t][0],qa_l[t][1],qa_l[t][2],qa_l[t][3], h2,h3);
            }
        }

        // ---- mask ----
        {
            uint2 m0 = *(const uint2*)(g_mpack + (size_t)q_lo*(SEQ/32) + (k0 >> 5));
            uint2 m1 = *(const uint2*)(g_mpack + (size_t)q_hi*(SEQ/32) + (k0 >> 5));
            uint64_t w0 = ((uint64_t)m0.y << 32) | m0.x;
            uint64_t w1 = ((uint64_t)m1.y << 32) | m1.x;
            #pragma unroll
            for (int j = 0; j < 8; j++) {
                int c = j*8 + 2*(l & 3);
                if (!((w0 >> c) & 1))     S[j][0] = -1e9f;
                if (!((w0 >> (c+1)) & 1)) S[j][1] = -1e9f;
                if (!((w1 >> c) & 1))     S[j][2] = -1e9f;
                if (!((w1 >> (c+1)) & 1)) S[j][3] = -1e9f;
            }
        }

        // ---- online softmax ----
        float mx0 = -1e30f, mx1 = -1e30f;
        #pragma unroll
        for (int j = 0; j < 8; j++) {
            mx0 = fmaxf(mx0, fmaxf(S[j][0], S[j][1]));
            mx1 = fmaxf(mx1, fmaxf(S[j][2], S[j][3]));
        }
        mx0 = fmaxf(mx0, __shfl_xor_sync(0xffffffffu, mx0, 1));
        mx0 = fmaxf(mx0, __shfl_xor_sync(0xffffffffu, mx0, 2));
        mx1 = fmaxf(mx1, __shfl_xor_sync(0xffffffffu, mx1, 1));
        mx1 = fmaxf(mx1, __shfl_xor_sync(0xffffffffu, mx1, 2));
        float mn0 = fmaxf(mr[0], mx0), mn1 = fmaxf(mr[1], mx1);
        float cr0 = __expf(mr[0] - mn0), cr1 = __expf(mr[1] - mn1);
        mr[0] = mn0; mr[1] = mn1;

        float ps0 = 0.f, ps1 = 0.f;
        uint32_t pa_h[4][4], pa_l[4][4];
        #pragma unroll
        for (int t = 0; t < 4; t++) {
            float p[8], lo[8];
            #pragma unroll
            for (int u = 0; u < 2; u++) {
                int j = 2*t + u;
                p[4*u+0] = __expf(S[j][0] - mn0);
                p[4*u+1] = __expf(S[j][1] - mn0);
                p[4*u+2] = __expf(S[j][2] - mn1);
                p[4*u+3] = __expf(S[j][3] - mn1);
                ps0 += p[4*u+0] + p[4*u+1];
                ps1 += p[4*u+2] + p[4*u+3];
            }
            #pragma unroll
            for (int e = 0; e < 8; e++) {
                float h, lw;
                split_bf16(p[e], h, lw);
                p[e] = h; lo[e] = lw;
            }
            pa_h[t][0] = pack_bf16(p[0], p[1]);
            pa_h[t][1] = pack_bf16(p[2], p[3]);
            pa_h[t][2] = pack_bf16(p[4], p[5]);
            pa_h[t][3] = pack_bf16(p[6], p[7]);
            pa_l[t][0] = pack_bf16(lo[0], lo[1]);
            pa_l[t][1] = pack_bf16(lo[2], lo[3]);
            pa_l[t][2] = pack_bf16(lo[4], lo[5]);
            pa_l[t][3] = pack_bf16(lo[6], lo[7]);
        }
        ps0 += __shfl_xor_sync(0xffffffffu, ps0, 1);
        ps0 += __shfl_xor_sync(0xffffffffu, ps0, 2);
        ps1 += __shfl_xor_sync(0xffffffffu, ps1, 1);
        ps1 += __shfl_xor_sync(0xffffffffu, ps1, 2);
        lr[0] = lr[0]*cr0 + ps0;
        lr[1] = lr[1]*cr1 + ps1;

        #pragma unroll
        for (int j = 0; j < 8; j++) {
            O[j][0] *= cr0; O[j][1] *= cr0;
            O[j][2] *= cr1; O[j][3] *= cr1;
        }

        // ---- O += P V  (V row-major, trans ldmatrix) ----
        #pragma unroll
        for (int t = 0; t < 4; t++) {
            #pragma unroll
            for (int g = 0; g < 4; g++) {
                uint32_t a = sbase + (t*16 + vrow_off)*RSTRIDE_B + g*32 + vcol_off;
                uint32_t h0,h1,h2,h3, l0,l1,l2,l3;
                LDSM_X4_T(h0,h1,h2,h3, a + oVh);
                LDSM_X4_T(l0,l1,l2,l3, a + oVl);
                MMA16816(O[2*g],   pa_h[t][0],pa_h[t][1],pa_h[t][2],pa_h[t][3], h0,h1);
                MMA16816(O[2*g],   pa_h[t][0],pa_h[t][1],pa_h[t][2],pa_h[t][3], l0,l1);
                MMA16816(O[2*g],   pa_l[t][0],pa_l[t][1],pa_l[t][2],pa_l[t][3], h0,h1);
                MMA16816(O[2*g+1], pa_h[t][0],pa_h[t][1],pa_h[t][2],pa_h[t][3], h2,h3);
                MMA16816(O[2*g+1], pa_h[t][0],pa_h[t][1],pa_h[t][2],pa_h[t][3], l2,l3);
                MMA16816(O[2*g+1], pa_l[t][0],pa_l[t][1],pa_l[t][2],pa_l[t][3], h2,h3);
            }
        }
        __syncthreads();
    }

    // ---- normalize + store bf16 hi/lo ----
    {
        float inv0 = 1.f / lr[0];
        float inv1 = 1.f / lr[1];
        uint32_t* yh0 = (uint32_t*)(g_aoh + (size_t)(b*SEQ + q_lo)*DK);
        uint32_t* yl0 = (uint32_t*)(g_aol + (size_t)(b*SEQ + q_lo)*DK);
        uint32_t* yh1 = (uint32_t*)(g_aoh + (size_t)(b*SEQ + q_hi)*DK);
        uint32_t* yl1 = (uint32_t*)(g_aol + (size_t)(b*SEQ + q_hi)*DK);
        #pragma unroll
        for (int j = 0; j < 8; j++) {
            float v0 = O[j][0]*inv0, v1 = O[j][1]*inv0;
            float v2 = O[j][2]*inv1, v3 = O[j][3]*inv1;
            float h0,lo0,h1f,lo1;
            split_bf16(v0, h0, lo0); split_bf16(v1, h1f, lo1);
            yh0[j*4 + (l & 3)] = pack_bf16(h0, h1f);
            yl0[j*4 + (l & 3)] = pack_bf16(lo0, lo1);
            split_bf16(v2, h0, lo0); split_bf16(v3, h1f, lo1);
            yh1[j*4 + (l & 3)] = pack_bf16(h0, h1f);
            yl1[j*4 + (l & 3)] = pack_bf16(lo0, lo1);
        }
    }
}

// ---------------------------------------------------------------------------
// Output projection on tensor cores: out[M,1024] = AO[M,64] @ Wo[1024,64]^T + bo
// CTA: 128 rows, n-chunks of 64. A-frags resident.
// smem: sAh(128x72) sAl sWh(64x72) sWl = 55296 B dynamic
// ---------------------------------------------------------------------------
__global__ __launch_bounds__(256, 1) void oproj_mma_kernel(
    const float* __restrict__ Wo, const float* __restrict__ bo,
    float* __restrict__ out)
{
    extern __shared__ char psm[];
    char* sAh = psm;
    char* sAl = psm + 128*RSTRIDE_B;
    char* sWh = psm + 256*RSTRIDE_B;
    char* sWl = psm + 320*RSTRIDE_B;

    const int tid = threadIdx.x;
    const int w = tid >> 5, l = tid & 31;
    const int row0 = blockIdx.x * 128;

    const uint32_t aAh = smem_u32(sAh);
    const uint32_t aWh = smem_u32(sWh), aWl = smem_u32(sWl);

    // stage A (bf16 hi/lo already)
    #pragma unroll
    for (int it = 0; it < 4; it++) {
        int i = tid + it*256;
        int r = i >> 3, c = i & 7;
        *(uint4*)(sAh + r*RSTRIDE_B + c*16) =
            ((const uint4*)(g_aoh + (size_t)(row0 + r)*DK))[c];
        *(uint4*)(sAl + r*RSTRIDE_B + c*16) =
            ((const uint4*)(g_aol + (size_t)(row0 + r)*DK))[c];
    }
    __syncthreads();

    uint32_t oa_h[4][4], oa_l[4][4];
    {
        int row = w*16 + (l & 7) + ((l >> 3) & 1)*8;
        int colb_off = ((l >> 3) & 2)*8;
        #pragma unroll
        for (int t = 0; t < 4; t++) {
            uint32_t a = aAh + row*RSTRIDE_B + t*32 + colb_off;
            LDSM_X4(oa_h[t][0], oa_h[t][1], oa_h[t][2], oa_h[t][3], a);
            LDSM_X4(oa_l[t][0], oa_l[t][1], oa_l[t][2], oa_l[t][3],
                    a + 128*RSTRIDE_B);
        }
    }
    __syncthreads();

    const int brow  = (l & 7) + ((l >> 3) & 2)*4;
    const int bcolb = ((l >> 3) & 1)*16;
    const int row_lo = row0 + w*16 + (l >> 2);
    const int row_hi = row_lo + 8;

    for (int n0 = 0; n0 < DM; n0 += 64) {
        // stage Wo chunk (fp32 -> bf16 hi/lo): rows n0..n0+63, k 0..63
        #pragma unroll
        for (int it = 0; it < 4; it++) {
            int i = tid + it*256;
            int r = i >> 4, c = i & 15;
            float4 wv = *(const float4*)(Wo + (size_t)(n0 + r)*DK + c*4);
            float h0,l0,h1,l1,h2,l2,h3,l3;
            split_bf16(wv.x, h0, l0); split_bf16(wv.y, h1, l1);
            split_bf16(wv.z, h2, l2); split_bf16(wv.w, h3, l3);
            uint2 uh = { pack_bf16(h0,h1), pack_bf16(h2,h3) };
            uint2 ul = { pack_bf16(l0,l1), pack_bf16(l2,l3) };
            *(uint2*)(sWh + r*RSTRIDE_B + c*8) = uh;
            *(uint2*)(sWl + r*RSTRIDE_B + c*8) = ul;
        }
        __syncthreads();

        float C[8][4];
        #pragma unroll
        for (int j = 0; j < 8; j++)
            #pragma unroll
            for (int i = 0; i < 4; i++) C[j][i] = 0.f;

        #pragma unroll
        for (int t = 0; t < 4; t++) {
            #pragma unroll
            for (int g = 0; g < 4; g++) {
                uint32_t ba = aWh + (g*16 + brow)*RSTRIDE_B + t*32 + bcolb;
                uint32_t h0,h1,h2,h3, w0,w1,w2,w3;
                LDSM_X4(h0,h1,h2,h3, ba);
                LDSM_X4(w0,w1,w2,w3, ba + (aWl - aWh));
                MMA16816(C[2*g],   oa_h[t][0],oa_h[t][1],oa_h[t][2],oa_h[t][3], h0,h1);
                MMA16816(C[2*g],   oa_h[t][0],oa_h[t][1],oa_h[t][2],oa_h[t][3], w0,w1);
                MMA16816(C[2*g],   oa_l[t][0],oa_l[t][1],oa_l[t][2],oa_l[t][3], h0,h1);
                MMA16816(C[2*g+1], oa_h[t][0],oa_h[t][1],oa_h[t][2],oa_h[t][3], h2,h3);
                MMA16816(C[2*g+1], oa_h[t][0],oa_h[t][1],oa_h[t][2],oa_h[t][3], w2,w3);
                MMA16816(C[2*g+1], oa_l[t][0],oa_l[t][1],oa_l[t][2],oa_l[t][3], h2,h3);
            }
        }

        // write this n-chunk
        float2* po0 = (float2*)(out + (size_t)row_lo*DM + n0);
        float2* po1 = (float2*)(out + (size_t)row_hi*DM + n0);
        #pragma unroll
        for (int j = 0; j < 8; j++) {
            int c = j*8 + 2*(l & 3);
            float b0v = bo[n0 + c], b1v = bo[n0 + c + 1];
            float2 v0 = { C[j][0] + b0v, C[j][1] + b1v };
            float2 v1 = { C[j][2] + b0v, C[j][3] + b1v };
            po0[j*4 + (l & 3)] = v0;
            po1[j*4 + (l & 3)] = v1;
        }
        __syncthreads();
    }
}

// ---------------------------------------------------------------------------
extern "C" void kernel_launch(void* const* d_in, const int* in_sizes, int n_in,
                              void* d_out, int out_size)
{
    const float* q    = (const float*)d_in[0];
    const float* k    = (const float*)d_in[1];
    const float* v    = (const float*)d_in[2];
    const int*   mask = (const int*)  d_in[3];
    const float* Wq   = (const float*)d_in[4];
    const float* bq   = (const float*)d_in[5];
    const float* Wk   = (const float*)d_in[6];
    const float* bk   = (const float*)d_in[7];
    const float* Wv   = (const float*)d_in[8];
    const float* bv   = (const float*)d_in[9];
    const float* Wo   = (const float*)d_in[10];
    const float* bo   = (const float*)d_in[11];
    float* out = (float*)d_out;

    const int psm_bytes = 384*RSTRIDE_B;   // 55296
    cudaFuncSetAttribute(proj_mma_kernel,
                         cudaFuncAttributeMaxDynamicSharedMemorySize, psm_bytes);
    cudaFuncSetAttribute(oproj_mma_kernel,
                         cudaFuncAttributeMaxDynamicSharedMemorySize, psm_bytes);

    pack_mask_kernel<<<SEQ*SEQ/32/8, 256>>>(mask);

    proj_mma_kernel<<<dim3(MTOT/128, 3), 256, psm_bytes>>>(
        q, k, v, Wq, Wk, Wv, bq, bk, bv);

    attn_mma_kernel<<<dim3(SEQ/128, BB), 256>>>();

    oproj_mma_kernel<<<MTOT/128, 256, psm_bytes>>>(Wo, bo, out);
}

// round 5
// speedup vs baseline: 2.6602x; 1.0772x over previous
#include <cuda_runtime.h>
#include <cuda_bf16.h>
#include <stdint.h>

#define BB 4
#define SEQ 4096
#define DM 1024
#define DK 64
#define MTOT (BB*SEQ)

#define RSTRIDE_B 144      // smem row stride in bytes (64 bf16 + 8 pad)

// ---------------------------------------------------------------------------
// Scratch (device globals — allocation-free)
// ---------------------------------------------------------------------------
__device__ alignas(16) __nv_bfloat16 g_qh_hi[MTOT*DK];
__device__ alignas(16) __nv_bfloat16 g_qh_lo[MTOT*DK];
__device__ alignas(16) __nv_bfloat16 g_kh_hi[MTOT*DK];
__device__ alignas(16) __nv_bfloat16 g_kh_lo[MTOT*DK];
__device__ alignas(16) __nv_bfloat16 g_vh_hi[MTOT*DK];
__device__ alignas(16) __nv_bfloat16 g_vh_lo[MTOT*DK];
__device__ alignas(16) __nv_bfloat16 g_aoh[MTOT*DK];
__device__ alignas(16) __nv_bfloat16 g_aol[MTOT*DK];
__device__ alignas(16) __nv_bfloat16 g_wh[4*64*1024];    // Wq,Wk,Wv,Wo hi
__device__ alignas(16) __nv_bfloat16 g_wl[4*64*1024];    // Wq,Wk,Wv,Wo lo
__device__ uint32_t g_mpack[SEQ*SEQ/32];

// ---------------------------------------------------------------------------
// helpers
// ---------------------------------------------------------------------------
__device__ __forceinline__ uint32_t smem_u32(const void* p) {
    uint32_t a;
    asm("{ .reg .u64 t; cvta.to.shared.u64 t, %1; cvt.u32.u64 %0, t; }"
        : "=r"(a) : "l"(p));
    return a;
}
__device__ __forceinline__ uint32_t pack_bf16(float a, float b) {
    __nv_bfloat162 h = __floats2bfloat162_rn(a, b);
    return *reinterpret_cast<uint32_t*>(&h);
}
__device__ __forceinline__ void split_bf16(float v, float& hi, float& lo) {
    __nv_bfloat16 h = __float2bfloat16(v);
    hi = __bfloat162float(h);
    lo = v - hi;
}

#define LDSM_X4(r0,r1,r2,r3,addr) \
    asm volatile("ldmatrix.sync.aligned.m8n8.x4.shared.b16 {%0,%1,%2,%3}, [%4];" \
        : "=r"(r0), "=r"(r1), "=r"(r2), "=r"(r3) : "r"(addr))

#define LDSM_X4_T(r0,r1,r2,r3,addr) \
    asm volatile("ldmatrix.sync.aligned.m8n8.x4.trans.shared.b16 {%0,%1,%2,%3}, [%4];" \
        : "=r"(r0), "=r"(r1), "=r"(r2), "=r"(r3) : "r"(addr))

#define MMA16816(c, a0,a1,a2,a3, b0,b1) \
    asm volatile("mma.sync.aligned.m16n8k16.row.col.f32.bf16.bf16.f32 " \
        "{%0,%1,%2,%3},{%4,%5,%6,%7},{%8,%9},{%0,%1,%2,%3};" \
        : "+f"((c)[0]), "+f"((c)[1]), "+f"((c)[2]), "+f"((c)[3]) \
        : "r"(a0), "r"(a1), "r"(a2), "r"(a3), "r"(b0), "r"(b1))

// ---------------------------------------------------------------------------
// mask bit-pack
// ---------------------------------------------------------------------------
__global__ __launch_bounds__(256) void pack_mask_kernel(const int* __restrict__ m)
{
    int w = blockIdx.x * 8 + (threadIdx.x >> 5);
    int lane = threadIdx.x & 31;
    int v = m[(size_t)w*32 + lane];
    uint32_t b = __ballot_sync(0xffffffffu, v != 0);
    if (lane == 0) g_mpack[w] = b;
}

// ---------------------------------------------------------------------------
// weight split: fp32 -> bf16 hi/lo, once. z: 0=Wq 1=Wk 2=Wv 3=Wo
// ---------------------------------------------------------------------------
__global__ __launch_bounds__(256) void split_w_kernel(
    const float* __restrict__ Wq, const float* __restrict__ Wk,
    const float* __restrict__ Wv, const float* __restrict__ Wo)
{
    int z = blockIdx.y;
    const float* W = (z == 0) ? Wq : (z == 1) ? Wk : (z == 2) ? Wv : Wo;
    int i4 = blockIdx.x * 256 + threadIdx.x;          // 0..16383
    float4 wv = ((const float4*)W)[i4];
    float h0,l0,h1,l1,h2,l2,h3,l3;
    split_bf16(wv.x, h0, l0); split_bf16(wv.y, h1, l1);
    split_bf16(wv.z, h2, l2); split_bf16(wv.w, h3, l3);
    uint2 uh = { pack_bf16(h0,h1), pack_bf16(h2,h3) };
    uint2 ul = { pack_bf16(l0,l1), pack_bf16(l2,l3) };
    ((uint2*)(g_wh + (size_t)z*65536))[i4] = uh;
    ((uint2*)(g_wl + (size_t)z*65536))[i4] = ul;
}

// ---------------------------------------------------------------------------
// Q/K/V projection on tensor cores (bf16x3).
// CTA: 64 rows, 128 threads (4 warps x 16 rows); grid (MTOT/64, 3).
// smem: sXh(64x144) sXl sWh sWl = 36864 B static
// ---------------------------------------------------------------------------
__global__ __launch_bounds__(128, 1) void proj_mma_kernel(
    const float* __restrict__ q, const float* __restrict__ k, const float* __restrict__ v,
    const float* __restrict__ bq, const float* __restrict__ bk, const float* __restrict__ bv)
{
    __shared__ alignas(16) char psm[4*64*RSTRIDE_B];
    char* sXh = psm;
    char* sXl = psm + 64*RSTRIDE_B;
    char* sWh = psm + 128*RSTRIDE_B;
    char* sWl = psm + 192*RSTRIDE_B;

    const int tid = threadIdx.x;
    const int w = tid >> 5, l = tid & 31;
    const int z = blockIdx.y;
    const int row0 = blockIdx.x * 64;

    const float* x    = (z == 0) ? q  : (z == 1) ? k  : v;
    const float* bias = (z == 0) ? bq : (z == 1) ? bk : bv;
    __nv_bfloat16* yh = (z == 0) ? g_qh_hi : (z == 1) ? g_kh_hi : g_vh_hi;
    __nv_bfloat16* yl = (z == 0) ? g_qh_lo : (z == 1) ? g_kh_lo : g_vh_lo;
    const __nv_bfloat16* gwh = g_wh + (size_t)z*65536;
    const __nv_bfloat16* gwl = g_wl + (size_t)z*65536;
    const float presc = (z == 0) ? 0.125f : 1.0f;

    const uint32_t aXh = smem_u32(sXh), aXl = smem_u32(sXl);
    const uint32_t aWh = smem_u32(sWh), aWl = smem_u32(sWl);

    const int arow  = w*16 + (l & 7) + ((l >> 3) & 1)*8;
    const int acolb = ((l >> 3) & 2)*8;
    const int brow  = (l & 7) + ((l >> 3) & 2)*4;
    const int bcolb = ((l >> 3) & 1)*16;

    float C[8][4];
    #pragma unroll
    for (int j = 0; j < 8; j++)
        #pragma unroll
        for (int i = 0; i < 4; i++) C[j][i] = 0.f;

    for (int k0 = 0; k0 < DM; k0 += 64) {
        // stage x chunk (fp32 -> bf16 hi/lo): 64 rows x 16 float4
        #pragma unroll
        for (int it = 0; it < 8; it++) {
            int i = tid + it*128;            // 0..1023
            int r = i >> 4, c = i & 15;
            float4 xv = *(const float4*)(x + (size_t)(row0 + r)*DM + k0 + c*4);
            float h0,l0,h1,l1,h2,l2,h3,l3;
            split_bf16(xv.x, h0, l0); split_bf16(xv.y, h1, l1);
            split_bf16(xv.z, h2, l2); split_bf16(xv.w, h3, l3);
            uint2 uh = { pack_bf16(h0,h1), pack_bf16(h2,h3) };
            uint2 ul = { pack_bf16(l0,l1), pack_bf16(l2,l3) };
            *(uint2*)(sXh + r*RSTRIDE_B + c*8) = uh;
            *(uint2*)(sXl + r*RSTRIDE_B + c*8) = ul;
        }
        // stage W chunk (already bf16): 64 rows x 8 uint4, hi + lo
        #pragma unroll
        for (int it = 0; it < 4; it++) {
            int i = tid + it*128;            // 0..511
            int r = i >> 3, c = i & 7;
            *(uint4*)(sWh + r*RSTRIDE_B + c*16) =
                ((const uint4*)(gwh + (size_t)r*DM + k0))[c];
            *(uint4*)(sWl + r*RSTRIDE_B + c*16) =
                ((const uint4*)(gwl + (size_t)r*DM + k0))[c];
        }
        __syncthreads();

        #pragma unroll
        for (int t = 0; t < 4; t++) {
            uint32_t ah[4], al[4];
            uint32_t aa = aXh + arow*RSTRIDE_B + t*32 + acolb;
            LDSM_X4(ah[0], ah[1], ah[2], ah[3], aa);
            LDSM_X4(al[0], al[1], al[2], al[3], aa + 64*RSTRIDE_B);
            #pragma unroll
            for (int g = 0; g < 4; g++) {
                uint32_t ba = aWh + (g*16 + brow)*RSTRIDE_B + t*32 + bcolb;
                uint32_t h0,h1,h2,h3, w0,w1,w2,w3;
                LDSM_X4(h0,h1,h2,h3, ba);
                LDSM_X4(w0,w1,w2,w3, ba + 64*RSTRIDE_B);
                MMA16816(C[2*g],   ah[0],ah[1],ah[2],ah[3], h0,h1);
                MMA16816(C[2*g],   ah[0],ah[1],ah[2],ah[3], w0,w1);
                MMA16816(C[2*g],   al[0],al[1],al[2],al[3], h0,h1);
                MMA16816(C[2*g+1], ah[0],ah[1],ah[2],ah[3], h2,h3);
                MMA16816(C[2*g+1], ah[0],ah[1],ah[2],ah[3], w2,w3);
                MMA16816(C[2*g+1], al[0],al[1],al[2],al[3], h2,h3);
            }
        }
        __syncthreads();
    }

    // epilogue
    const int row_lo = row0 + w*16 + (l >> 2);
    const int row_hi = row_lo + 8;
    uint32_t* yh0 = (uint32_t*)(yh + (size_t)row_lo*DK);
    uint32_t* yl0 = (uint32_t*)(yl + (size_t)row_lo*DK);
    uint32_t* yh1 = (uint32_t*)(yh + (size_t)row_hi*DK);
    uint32_t* yl1 = (uint32_t*)(yl + (size_t)row_hi*DK);
    #pragma unroll
    for (int j = 0; j < 8; j++) {
        int c = j*8 + 2*(l & 3);
        float b0 = bias[c], b1 = bias[c+1];
        float v0 = (C[j][0] + b0)*presc, v1 = (C[j][1] + b1)*presc;
        float v2 = (C[j][2] + b0)*presc, v3 = (C[j][3] + b1)*presc;
        float h,lo0,h1f,lo1;
        split_bf16(v0, h, lo0); split_bf16(v1, h1f, lo1);
        yh0[j*4 + (l & 3)] = pack_bf16(h, h1f);
        yl0[j*4 + (l & 3)] = pack_bf16(lo0, lo1);
        split_bf16(v2, h, lo0); split_bf16(v3, h1f, lo1);
        yh1[j*4 + (l & 3)] = pack_bf16(h, h1f);
        yl1[j*4 + (l & 3)] = pack_bf16(lo0, lo1);
    }
}

// ---------------------------------------------------------------------------
// Flash attention via mma.sync (bf16x3). CTA = 64 q x 128 thr (4 warps x 16).
// ---------------------------------------------------------------------------
__global__ __launch_bounds__(128, 1) void attn_mma_kernel()
{
    __shared__ alignas(16) char sbuf[4*64*RSTRIDE_B];   // 36864 B

    const int tid = threadIdx.x;
    const int w   = tid >> 5;
    const int l   = tid & 31;
    const int b   = blockIdx.y;
    const int q0  = blockIdx.x * 64;

    const uint32_t sbase = smem_u32(sbuf);
    const uint32_t oQl = 64*RSTRIDE_B;   // Q lo during prologue
    const uint32_t oKh = 0;
    const uint32_t oKl = 64*RSTRIDE_B;
    const uint32_t oVh = 128*RSTRIDE_B;
    const uint32_t oVl = 192*RSTRIDE_B;

    // ---------------- Q fragments (once) ----------------
    {
        const uint4* gqh = (const uint4*)(g_qh_hi + (size_t)(b*SEQ + q0)*DK);
        const uint4* gql = (const uint4*)(g_qh_lo + (size_t)(b*SEQ + q0)*DK);
        #pragma unroll
        for (int it = 0; it < 4; it++) {
            int i = tid + it*128;            // 0..511
            int r = i >> 3, c = i & 7;
            *(uint4*)(sbuf + r*RSTRIDE_B + c*16) = gqh[i];
            *(uint4*)(sbuf + oQl + r*RSTRIDE_B + c*16) = gql[i];
        }
    }
    __syncthreads();

    uint32_t qa_h[4][4], qa_l[4][4];
    {
        int row = w*16 + (l & 7) + ((l >> 3) & 1)*8;
        int colb_off = ((l >> 3) & 2)*8;
        #pragma unroll
        for (int t = 0; t < 4; t++) {
            uint32_t a = sbase + row*RSTRIDE_B + t*32 + colb_off;
            LDSM_X4(qa_h[t][0], qa_h[t][1], qa_h[t][2], qa_h[t][3], a);
            LDSM_X4(qa_l[t][0], qa_l[t][1], qa_l[t][2], qa_l[t][3], a + oQl);
        }
    }
    __syncthreads();

    const int brow_off = (l & 7) + ((l >> 3) & 2)*4;
    const int bcol_off = ((l >> 3) & 1)*16;
    const int vrow_off = (l & 7) + ((l >> 3) & 1)*8;
    const int vcol_off = ((l >> 4) & 1)*16;

    float O[8][4];
    #pragma unroll
    for (int j = 0; j < 8; j++)
        #pragma unroll
        for (int i = 0; i < 4; i++) O[j][i] = 0.f;
    float mr[2] = {-1e30f, -1e30f};
    float lr[2] = {0.f, 0.f};

    const int q_lo = q0 + w*16 + (l >> 2);
    const int q_hi = q_lo + 8;

    const uint4* gkh = (const uint4*)(g_kh_hi + (size_t)b*SEQ*DK);
    const uint4* gkl = (const uint4*)(g_kh_lo + (size_t)b*SEQ*DK);
    const uint4* gvh = (const uint4*)(g_vh_hi + (size_t)b*SEQ*DK);
    const uint4* gvl = (const uint4*)(g_vh_lo + (size_t)b*SEQ*DK);

    for (int k0 = 0; k0 < SEQ; k0 += 64) {
        // stage K and V tiles
        #pragma unroll
        for (int it = 0; it < 4; it++) {
            int i = tid + it*128;            // 0..511
            int r = i >> 3, c = i & 7;
            uint32_t d = r*RSTRIDE_B + c*16;
            size_t gi = (size_t)(k0 + r)*8 + c;
            *(uint4*)(sbuf + oKh + d) = gkh[gi];
            *(uint4*)(sbuf + oKl + d) = gkl[gi];
            *(uint4*)(sbuf + oVh + d) = gvh[gi];
            *(uint4*)(sbuf + oVl + d) = gvl[gi];
        }
        __syncthreads();

        // ---- S = Q K^T ----
        float S[8][4];
        #pragma unroll
        for (int j = 0; j < 8; j++)
            #pragma unroll
            for (int i = 0; i < 4; i++) S[j][i] = 0.f;

        #pragma unroll
        for (int t = 0; t < 4; t++) {
            #pragma unroll
            for (int g = 0; g < 4; g++) {
                uint32_t a = sbase + (g*16 + brow_off)*RSTRIDE_B + t*32 + bcol_off;
                uint32_t h0,h1,h2,h3, l0,l1,l2,l3;
                LDSM_X4(h0,h1,h2,h3, a + oKh);
                LDSM_X4(l0,l1,l2,l3, a + oKl);
                MMA16816(S[2*g],   qa_h[t][0],qa_h[t][1],qa_h[t][2],qa_h[t][3], h0,h1);
                MMA16816(S[2*g],   qa_h[t][0],qa_h[t][1],qa_h[t][2],qa_h[t][3], l0,l1);
                MMA16816(S[2*g],   qa_l[t][0],qa_l[t][1],qa_l[t][2],qa_l[t][3], h0,h1);
                MMA16816(S[2*g+1], qa_h[t][0],qa_h[t][1],qa_h[t][2],qa_h[t][3], h2,h3);
                MMA16816(S[2*g+1], qa_h[t][0],qa_h[t][1],qa_h[t][2],qa_h[t][3], l2,l3);
                MMA16816(S[2*g+1], qa_l[t][0],qa_l[t][1],qa_l[t][2],qa_l[t][3], h2,h3);
            }
        }

        // ---- mask ----
        {
            uint2 m0 = *(const uint2*)(g_mpack + (size_t)q_lo*(SEQ/32) + (k0 >> 5));
            uint2 m1 = *(const uint2*)(g_mpack + (size_t)q_hi*(SEQ/32) + (k0 >> 5));
            uint64_t w0 = ((uint64_t)m0.y << 32) | m0.x;
            uint64_t w1 = ((uint64_t)m1.y << 32) | m1.x;
            #pragma unroll
            for (int j = 0; j < 8; j++) {
                int c = j*8 + 2*(l & 3);
                if (!((w0 >> c) & 1))     S[j][0] = -1e9f;
                if (!((w0 >> (c+1)) & 1)) S[j][1] = -1e9f;
                if (!((w1 >> c) & 1))     S[j][2] = -1e9f;
                if (!((w1 >> (c+1)) & 1)) S[j][3] = -1e9f;
            }
        }

        // ---- online softmax ----
        float mx0 = -1e30f, mx1 = -1e30f;
        #pragma unroll
        for (int j = 0; j < 8; j++) {
            mx0 = fmaxf(mx0, fmaxf(S[j][0], S[j][1]));
            mx1 = fmaxf(mx1, fmaxf(S[j][2], S[j][3]));
        }
        mx0 = fmaxf(mx0, __shfl_xor_sync(0xffffffffu, mx0, 1));
        mx0 = fmaxf(mx0, __shfl_xor_sync(0xffffffffu, mx0, 2));
        mx1 = fmaxf(mx1, __shfl_xor_sync(0xffffffffu, mx1, 1));
        mx1 = fmaxf(mx1, __shfl_xor_sync(0xffffffffu, mx1, 2));
        float mn0 = fmaxf(mr[0], mx0), mn1 = fmaxf(mr[1], mx1);
        float cr0 = __expf(mr[0] - mn0), cr1 = __expf(mr[1] - mn1);
        mr[0] = mn0; mr[1] = mn1;

        float ps0 = 0.f, ps1 = 0.f;
        uint32_t pa_h[4][4], pa_l[4][4];
        #pragma unroll
        for (int t = 0; t < 4; t++) {
            float p[8], lo[8];
            #pragma unroll
            for (int u = 0; u < 2; u++) {
                int j = 2*t + u;
                p[4*u+0] = __expf(S[j][0] - mn0);
                p[4*u+1] = __expf(S[j][1] - mn0);
                p[4*u+2] = __expf(S[j][2] - mn1);
                p[4*u+3] = __expf(S[j][3] - mn1);
                ps0 += p[4*u+0] + p[4*u+1];
                ps1 += p[4*u+2] + p[4*u+3];
            }
            #pragma unroll
            for (int e = 0; e < 8; e++) {
                float h, lw;
                split_bf16(p[e], h, lw);
                p[e] = h; lo[e] = lw;
            }
            pa_h[t][0] = pack_bf16(p[0], p[1]);
            pa_h[t][1] = pack_bf16(p[2], p[3]);
            pa_h[t][2] = pack_bf16(p[4], p[5]);
            pa_h[t][3] = pack_bf16(p[6], p[7]);
            pa_l[t][0] = pack_bf16(lo[0], lo[1]);
            pa_l[t][1] = pack_bf16(lo[2], lo[3]);
            pa_l[t][2] = pack_bf16(lo[4], lo[5]);
            pa_l[t][3] = pack_bf16(lo[6], lo[7]);
        }
        ps0 += __shfl_xor_sync(0xffffffffu, ps0, 1);
        ps0 += __shfl_xor_sync(0xffffffffu, ps0, 2);
        ps1 += __shfl_xor_sync(0xffffffffu, ps1, 1);
        ps1 += __shfl_xor_sync(0xffffffffu, ps1, 2);
        lr[0] = lr[0]*cr0 + ps0;
        lr[1] = lr[1]*cr1 + ps1;

        #pragma unroll
        for (int j = 0; j < 8; j++) {
            O[j][0] *= cr0; O[j][1] *= cr0;
            O[j][2] *= cr1; O[j][3] *= cr1;
        }

        // ---- O += P V ----
        #pragma unroll
        for (int t = 0; t < 4; t++) {
            #pragma unroll
            for (int g = 0; g < 4; g++) {
                uint32_t a = sbase + (t*16 + vrow_off)*RSTRIDE_B + g*32 + vcol_off;
                uint32_t h0,h1,h2,h3, l0,l1,l2,l3;
                LDSM_X4_T(h0,h1,h2,h3, a + oVh);
                LDSM_X4_T(l0,l1,l2,l3, a + oVl);
                MMA16816(O[2*g],   pa_h[t][0],pa_h[t][1],pa_h[t][2],pa_h[t][3], h0,h1);
                MMA16816(O[2*g],   pa_h[t][0],pa_h[t][1],pa_h[t][2],pa_h[t][3], l0,l1);
                MMA16816(O[2*g],   pa_l[t][0],pa_l[t][1],pa_l[t][2],pa_l[t][3], h0,h1);
                MMA16816(O[2*g+1], pa_h[t][0],pa_h[t][1],pa_h[t][2],pa_h[t][3], h2,h3);
                MMA16816(O[2*g+1], pa_h[t][0],pa_h[t][1],pa_h[t][2],pa_h[t][3], l2,l3);
                MMA16816(O[2*g+1], pa_l[t][0],pa_l[t][1],pa_l[t][2],pa_l[t][3], h2,h3);
            }
        }
        __syncthreads();
    }

    // ---- normalize + store bf16 hi/lo ----
    {
        float inv0 = 1.f / lr[0];
        float inv1 = 1.f / lr[1];
        uint32_t* yh0 = (uint32_t*)(g_aoh + (size_t)(b*SEQ + q_lo)*DK);
        uint32_t* yl0 = (uint32_t*)(g_aol + (size_t)(b*SEQ + q_lo)*DK);
        uint32_t* yh1 = (uint32_t*)(g_aoh + (size_t)(b*SEQ + q_hi)*DK);
        uint32_t* yl1 = (uint32_t*)(g_aol + (size_t)(b*SEQ + q_hi)*DK);
        #pragma unroll
        for (int j = 0; j < 8; j++) {
            float v0 = O[j][0]*inv0, v1 = O[j][1]*inv0;
            float v2 = O[j][2]*inv1, v3 = O[j][3]*inv1;
            float h0,lo0,h1f,lo1;
            split_bf16(v0, h0, lo0); split_bf16(v1, h1f, lo1);
            yh0[j*4 + (l & 3)] = pack_bf16(h0, h1f);
            yl0[j*4 + (l & 3)] = pack_bf16(lo0, lo1);
            split_bf16(v2, h0, lo0); split_bf16(v3, h1f, lo1);
            yh1[j*4 + (l & 3)] = pack_bf16(h0, h1f);
            yl1[j*4 + (l & 3)] = pack_bf16(lo0, lo1);
        }
    }
}

// ---------------------------------------------------------------------------
// Output projection: out[M,1024] = AO[M,64] @ Wo[1024,64]^T + bo
// CTA: 64 rows, 128 threads; grid MTOT/64. Wo pre-split.
// ---------------------------------------------------------------------------
__global__ __launch_bounds__(128, 1) void oproj_mma_kernel(
    const float* __restrict__ bo, float* __restrict__ out)
{
    __shared__ alignas(16) char psm[4*64*RSTRIDE_B];
    char* sAh = psm;
    char* sAl = psm + 64*RSTRIDE_B;
    char* sWh = psm + 128*RSTRIDE_B;
    char* sWl = psm + 192*RSTRIDE_B;

    const int tid = threadIdx.x;
    const int w = tid >> 5, l = tid & 31;
    const int row0 = blockIdx.x * 64;

    const __nv_bfloat16* gwh = g_wh + (size_t)3*65536;   // Wo hi [1024][64]
    const __nv_bfloat16* gwl = g_wl + (size_t)3*65536;

    const uint32_t aAh = smem_u32(sAh);
    const uint32_t aWh = smem_u32(sWh);

    // stage A hi/lo
    #pragma unroll
    for (int it = 0; it < 4; it++) {
        int i = tid + it*128;
        int r = i >> 3, c = i & 7;
        *(uint4*)(sAh + r*RSTRIDE_B + c*16) =
            ((const uint4*)(g_aoh + (size_t)(row0 + r)*DK))[c];
        *(uint4*)(sAl + r*RSTRIDE_B + c*16) =
            ((const uint4*)(g_aol + (size_t)(row0 + r)*DK))[c];
    }
    __syncthreads();

    uint32_t oa_h[4][4], oa_l[4][4];
    {
        int row = w*16 + (l & 7) + ((l >> 3) & 1)*8;
        int colb_off = ((l >> 3) & 2)*8;
        #pragma unroll
        for (int t = 0; t < 4; t++) {
            uint32_t a = aAh + row*RSTRIDE_B + t*32 + colb_off;
            LDSM_X4(oa_h[t][0], oa_h[t][1], oa_h[t][2], oa_h[t][3], a);
            LDSM_X4(oa_l[t][0], oa_l[t][1], oa_l[t][2], oa_l[t][3], a + 64*RSTRIDE_B);
        }
    }
    __syncthreads();

    const int brow  = (l & 7) + ((l >> 3) & 2)*4;
    const int bcolb = ((l >> 3) & 1)*16;
    const int row_lo = row0 + w*16 + (l >> 2);
    const int row_hi = row_lo + 8;

    for (int n0 = 0; n0 < DM; n0 += 64) {
        // stage Wo chunk (bf16): rows n0..n0+63 x 8 uint4, hi + lo
        #pragma unroll
        for (int it = 0; it < 4; it++) {
            int i = tid + it*128;
            int r = i >> 3, c = i & 7;
            *(uint4*)(sWh + r*RSTRIDE_B + c*16) =
                ((const uint4*)(gwh + (size_t)(n0 + r)*DK))[c];
            *(uint4*)(sWl + r*RSTRIDE_B + c*16) =
                ((const uint4*)(gwl + (size_t)(n0 + r)*DK))[c];
        }
        __syncthreads();

        float C[8][4];
        #pragma unroll
        for (int j = 0; j < 8; j++)
            #pragma unroll
            for (int i = 0; i < 4; i++) C[j][i] = 0.f;

        #pragma unroll
        for (int t = 0; t < 4; t++) {
            #pragma unroll
            for (int g = 0; g < 4; g++) {
                uint32_t ba = aWh + (g*16 + brow)*RSTRIDE_B + t*32 + bcolb;
                uint32_t h0,h1,h2,h3, w0,w1,w2,w3;
                LDSM_X4(h0,h1,h2,h3, ba);
                LDSM_X4(w0,w1,w2,w3, ba + 64*RSTRIDE_B);
                MMA16816(C[2*g],   oa_h[t][0],oa_h[t][1],oa_h[t][2],oa_h[t][3], h0,h1);
                MMA16816(C[2*g],   oa_h[t][0],oa_h[t][1],oa_h[t][2],oa_h[t][3], w0,w1);
                MMA16816(C[2*g],   oa_l[t][0],oa_l[t][1],oa_l[t][2],oa_l[t][3], h0,h1);
                MMA16816(C[2*g+1], oa_h[t][0],oa_h[t][1],oa_h[t][2],oa_h[t][3], h2,h3);
                MMA16816(C[2*g+1], oa_h[t][0],oa_h[t][1],oa_h[t][2],oa_h[t][3], w2,w3);
                MMA16816(C[2*g+1], oa_l[t][0],oa_l[t][1],oa_l[t][2],oa_l[t][3], h2,h3);
            }
        }

        float2* po0 = (float2*)(out + (size_t)row_lo*DM + n0);
        float2* po1 = (float2*)(out + (size_t)row_hi*DM + n0);
        #pragma unroll
        for (int j = 0; j < 8; j++) {
            int c = j*8 + 2*(l & 3);
            float b0v = bo[n0 + c], b1v = bo[n0 + c + 1];
            float2 v0 = { C[j][0] + b0v, C[j][1] + b1v };
            float2 v1 = { C[j][2] + b0v, C[j][3] + b1v };
            po0[j*4 + (l & 3)] = v0;
            po1[j*4 + (l & 3)] = v1;
        }
        __syncthreads();
    }
}

// ---------------------------------------------------------------------------
extern "C" void kernel_launch(void* const* d_in, const int* in_sizes, int n_in,
                              void* d_out, int out_size)
{
    const float* q    = (const float*)d_in[0];
    const float* k    = (const float*)d_in[1];
    const float* v    = (const float*)d_in[2];
    const int*   mask = (const int*)  d_in[3];
    const float* Wq   = (const float*)d_in[4];
    const float* bq   = (const float*)d_in[5];
    const float* Wk   = (const float*)d_in[6];
    const float* bk   = (const float*)d_in[7];
    const float* Wv   = (const float*)d_in[8];
    const float* bv   = (const float*)d_in[9];
    const float* Wo   = (const float*)d_in[10];
    const float* bo   = (const float*)d_in[11];
    float* out = (float*)d_out;

    pack_mask_kernel<<<SEQ*SEQ/32/8, 256>>>(mask);
    split_w_kernel<<<dim3(64, 4), 256>>>(Wq, Wk, Wv, Wo);

    proj_mma_kernel<<<dim3(MTOT/64, 3), 128>>>(q, k, v, bq, bk, bv);

    attn_mma_kernel<<<dim3(SEQ/64, BB), 128>>>();

    oproj_mma_kernel<<<MTOT/64, 128>>>(bo, out);
}

// round 6
// speedup vs baseline: 2.9560x; 1.1112x over previous
#include <cuda_runtime.h>
#include <cuda_bf16.h>
#include <stdint.h>

#define BB 4
#define SEQ 4096
#define DM 1024
#define DK 64
#define MTOT (BB*SEQ)

#define RSTRIDE_B 144      // smem row stride in bytes (64 bf16 + 8 pad)
#define TILE_B    9216     // 64 rows * 144 B
#define ABUF_B    36864    // one attn K/V buffer (Kh,Kl,Vh,Vl)

// ---------------------------------------------------------------------------
// Scratch (device globals — allocation-free)
// ---------------------------------------------------------------------------
__device__ alignas(16) __nv_bfloat16 g_qh_hi[MTOT*DK];
__device__ alignas(16) __nv_bfloat16 g_qh_lo[MTOT*DK];
__device__ alignas(16) __nv_bfloat16 g_kh_hi[MTOT*DK];
__device__ alignas(16) __nv_bfloat16 g_kh_lo[MTOT*DK];
__device__ alignas(16) __nv_bfloat16 g_vh_hi[MTOT*DK];
__device__ alignas(16) __nv_bfloat16 g_vh_lo[MTOT*DK];
__device__ alignas(16) __nv_bfloat16 g_aoh[MTOT*DK];
__device__ alignas(16) __nv_bfloat16 g_aol[MTOT*DK];
__device__ alignas(16) __nv_bfloat16 g_wh[4*64*1024];
__device__ alignas(16) __nv_bfloat16 g_wl[4*64*1024];
__device__ uint32_t g_mpack[SEQ*SEQ/32];

// ---------------------------------------------------------------------------
// helpers
// ---------------------------------------------------------------------------
__device__ __forceinline__ uint32_t smem_u32(const void* p) {
    uint32_t a;
    asm("{ .reg .u64 t; cvta.to.shared.u64 t, %1; cvt.u32.u64 %0, t; }"
        : "=r"(a) : "l"(p));
    return a;
}
__device__ __forceinline__ uint32_t pack_bf16(float a, float b) {
    __nv_bfloat162 h = __floats2bfloat162_rn(a, b);
    return *reinterpret_cast<uint32_t*>(&h);
}
__device__ __forceinline__ void split_bf16(float v, float& hi, float& lo) {
    __nv_bfloat16 h = __float2bfloat16(v);
    hi = __bfloat162float(h);
    lo = v - hi;
}

#define LDSM_X4(r0,r1,r2,r3,addr) \
    asm volatile("ldmatrix.sync.aligned.m8n8.x4.shared.b16 {%0,%1,%2,%3}, [%4];" \
        : "=r"(r0), "=r"(r1), "=r"(r2), "=r"(r3) : "r"(addr))

#define LDSM_X4_T(r0,r1,r2,r3,addr) \
    asm volatile("ldmatrix.sync.aligned.m8n8.x4.trans.shared.b16 {%0,%1,%2,%3}, [%4];" \
        : "=r"(r0), "=r"(r1), "=r"(r2), "=r"(r3) : "r"(addr))

#define MMA16816(c, a0,a1,a2,a3, b0,b1) \
    asm volatile("mma.sync.aligned.m16n8k16.row.col.f32.bf16.bf16.f32 " \
        "{%0,%1,%2,%3},{%4,%5,%6,%7},{%8,%9},{%0,%1,%2,%3};" \
        : "+f"((c)[0]), "+f"((c)[1]), "+f"((c)[2]), "+f"((c)[3]) \
        : "r"(a0), "r"(a1), "r"(a2), "r"(a3), "r"(b0), "r"(b1))

#define CP16(dst_u32, src_ptr) \
    asm volatile("cp.async.cg.shared.global [%0], [%1], 16;" \
        :: "r"(dst_u32), "l"(src_ptr) : "memory")
#define CP_COMMIT() asm volatile("cp.async.commit_group;" ::: "memory")
#define CP_WAIT(N)  asm volatile("cp.async.wait_group %0;" :: "n"(N) : "memory")

// ---------------------------------------------------------------------------
// mask bit-pack
// ---------------------------------------------------------------------------
__global__ __launch_bounds__(256) void pack_mask_kernel(const int* __restrict__ m)
{
    int w = blockIdx.x * 8 + (threadIdx.x >> 5);
    int lane = threadIdx.x & 31;
    int v = m[(size_t)w*32 + lane];
    uint32_t b = __ballot_sync(0xffffffffu, v != 0);
    if (lane == 0) g_mpack[w] = b;
}

// ---------------------------------------------------------------------------
// weight split: fp32 -> bf16 hi/lo. z: 0=Wq 1=Wk 2=Wv 3=Wo
// ---------------------------------------------------------------------------
__global__ __launch_bounds__(256) void split_w_kernel(
    const float* __restrict__ Wq, const float* __restrict__ Wk,
    const float* __restrict__ Wv, const float* __restrict__ Wo)
{
    int z = blockIdx.y;
    const float* W = (z == 0) ? Wq : (z == 1) ? Wk : (z == 2) ? Wv : Wo;
    int i4 = blockIdx.x * 256 + threadIdx.x;
    float4 wv = ((const float4*)W)[i4];
    float h0,l0,h1,l1,h2,l2,h3,l3;
    split_bf16(wv.x, h0, l0); split_bf16(wv.y, h1, l1);
    split_bf16(wv.z, h2, l2); split_bf16(wv.w, h3, l3);
    uint2 uh = { pack_bf16(h0,h1), pack_bf16(h2,h3) };
    uint2 ul = { pack_bf16(l0,l1), pack_bf16(l2,l3) };
    ((uint2*)(g_wh + (size_t)z*65536))[i4] = uh;
    ((uint2*)(g_wl + (size_t)z*65536))[i4] = ul;
}

// ---------------------------------------------------------------------------
// Q/K/V projection (bf16x3). CTA: 64 rows, 128 threads; grid (MTOT/64, 3).
// x prefetched into regs one chunk ahead; W double-buffered via cp.async.
// dyn smem: sXh 0, sXl 9216, Wbuf0 {h:18432, l:27648}, Wbuf1 {h:36864, l:46080}
// ---------------------------------------------------------------------------
__global__ __launch_bounds__(128, 1) void proj_mma_kernel(
    const float* __restrict__ q, const float* __restrict__ k, const float* __restrict__ v,
    const float* __restrict__ bq, const float* __restrict__ bk, const float* __restrict__ bv)
{
    extern __shared__ char psm[];
    const uint32_t sb = smem_u32(psm);
    const uint32_t oXh = 0, oXl = TILE_B;

    const int tid = threadIdx.x;
    const int w = tid >> 5, l = tid & 31;
    const int z = blockIdx.y;
    const int row0 = blockIdx.x * 64;

    const float* x    = (z == 0) ? q  : (z == 1) ? k  : v;
    const float* bias = (z == 0) ? bq : (z == 1) ? bk : bv;
    __nv_bfloat16* yh = (z == 0) ? g_qh_hi : (z == 1) ? g_kh_hi : g_vh_hi;
    __nv_bfloat16* yl = (z == 0) ? g_qh_lo : (z == 1) ? g_kh_lo : g_vh_lo;
    const __nv_bfloat16* gwh = g_wh + (size_t)z*65536;
    const __nv_bfloat16* gwl = g_wl + (size_t)z*65536;
    // fold 1/sqrt(dk) * log2(e) into Q; K/V get plain values.
    const float presc = (z == 0) ? 0.125f*1.44269504f : 1.0f;

    const int arow  = w*16 + (l & 7) + ((l >> 3) & 1)*8;
    const int acolb = ((l >> 3) & 2)*8;
    const int brow  = (l & 7) + ((l >> 3) & 2)*4;
    const int bcolb = ((l >> 3) & 1)*16;

    const int xr_r = tid >> 4;          // rows handled by this thread: xr_r, +8..(8 chunks)
    const int xr_c = tid & 15;

    float C[8][4];
    #pragma unroll
    for (int j = 0; j < 8; j++)
        #pragma unroll
        for (int i = 0; i < 4; i++) C[j][i] = 0.f;

    // W chunk 0 -> wbuf0
    {
        #pragma unroll
        for (int it = 0; it < 4; it++) {
            int i = tid + it*128;
            int r = i >> 3, c = i & 7;
            uint32_t d = r*RSTRIDE_B + c*16;
            CP16(sb + 2*TILE_B + d, ((const uint4*)(gwh + (size_t)r*DM)) + c);
            CP16(sb + 3*TILE_B + d, ((const uint4*)(gwl + (size_t)r*DM)) + c);
        }
        CP_COMMIT();
    }
    // x chunk 0 -> regs
    float4 xr[8];
    #pragma unroll
    for (int it = 0; it < 8; it++) {
        int r = xr_r + it*8;
        xr[it] = *(const float4*)(x + (size_t)(row0 + r)*DM + xr_c*4);
    }

    for (int k0 = 0; k0 < DM; k0 += 64) {
        int kc = k0 >> 6;
        // convert x regs -> smem hi/lo
        #pragma unroll
        for (int it = 0; it < 8; it++) {
            int r = xr_r + it*8;
            float h0,l0,h1,l1,h2,l2,h3,l3;
            split_bf16(xr[it].x, h0, l0); split_bf16(xr[it].y, h1, l1);
            split_bf16(xr[it].z, h2, l2); split_bf16(xr[it].w, h3, l3);
            uint2 uh = { pack_bf16(h0,h1), pack_bf16(h2,h3) };
            uint2 ul = { pack_bf16(l0,l1), pack_bf16(l2,l3) };
            *(uint2*)(psm + oXh + r*RSTRIDE_B + xr_c*8) = uh;
            *(uint2*)(psm + oXl + r*RSTRIDE_B + xr_c*8) = ul;
        }
        // prefetch next x chunk into regs (latency hidden behind MMAs)
        if (k0 + 64 < DM) {
            #pragma unroll
            for (int it = 0; it < 8; it++) {
                int r = xr_r + it*8;
                xr[it] = *(const float4*)(x + (size_t)(row0 + r)*DM + k0 + 64 + xr_c*4);
            }
        }
        // prefetch next W chunk; wait for current
        if (k0 + 64 < DM) {
            uint32_t wb = sb + 2*TILE_B + ((kc+1)&1)*2*TILE_B;
            #pragma unroll
            for (int it = 0; it < 4; it++) {
                int i = tid + it*128;
                int r = i >> 3, c = i & 7;
                uint32_t d = r*RSTRIDE_B + c*16;
                CP16(wb + d,          ((const uint4*)(gwh + (size_t)r*DM + k0 + 64)) + c);
                CP16(wb + TILE_B + d, ((const uint4*)(gwl + (size_t)r*DM + k0 + 64)) + c);
            }
            CP_COMMIT();
            CP_WAIT(1);
        } else {
            CP_WAIT(0);
        }
        __syncthreads();

        const uint32_t aWh = sb + 2*TILE_B + (kc&1)*2*TILE_B;
        #pragma unroll
        for (int t = 0; t < 4; t++) {
            uint32_t ah[4], al[4];
            uint32_t aa = sb + oXh + arow*RSTRIDE_B + t*32 + acolb;
            LDSM_X4(ah[0], ah[1], ah[2], ah[3], aa);
            LDSM_X4(al[0], al[1], al[2], al[3], aa + TILE_B);
            #pragma unroll
            for (int g = 0; g < 4; g++) {
                uint32_t ba = aWh + (g*16 + brow)*RSTRIDE_B + t*32 + bcolb;
                uint32_t h0,h1,h2,h3, w0,w1,w2,w3;
                LDSM_X4(h0,h1,h2,h3, ba);
                LDSM_X4(w0,w1,w2,w3, ba + TILE_B);
                MMA16816(C[2*g],   ah[0],ah[1],ah[2],ah[3], h0,h1);
                MMA16816(C[2*g],   ah[0],ah[1],ah[2],ah[3], w0,w1);
                MMA16816(C[2*g],   al[0],al[1],al[2],al[3], h0,h1);
                MMA16816(C[2*g+1], ah[0],ah[1],ah[2],ah[3], h2,h3);
                MMA16816(C[2*g+1], ah[0],ah[1],ah[2],ah[3], w2,w3);
                MMA16816(C[2*g+1], al[0],al[1],al[2],al[3], h2,h3);
            }
        }
        __syncthreads();
    }

    // epilogue
    const int row_lo = row0 + w*16 + (l >> 2);
    const int row_hi = row_lo + 8;
    uint32_t* yh0 = (uint32_t*)(yh + (size_t)row_lo*DK);
    uint32_t* yl0 = (uint32_t*)(yl + (size_t)row_lo*DK);
    uint32_t* yh1 = (uint32_t*)(yh + (size_t)row_hi*DK);
    uint32_t* yl1 = (uint32_t*)(yl + (size_t)row_hi*DK);
    #pragma unroll
    for (int j = 0; j < 8; j++) {
        int c = j*8 + 2*(l & 3);
        float b0 = bias[c], b1 = bias[c+1];
        float v0 = (C[j][0] + b0)*presc, v1 = (C[j][1] + b1)*presc;
        float v2 = (C[j][2] + b0)*presc, v3 = (C[j][3] + b1)*presc;
        float h,lo0,h1f,lo1;
        split_bf16(v0, h, lo0); split_bf16(v1, h1f, lo1);
        yh0[j*4 + (l & 3)] = pack_bf16(h, h1f);
        yl0[j*4 + (l & 3)] = pack_bf16(lo0, lo1);
        split_bf16(v2, h, lo0); split_bf16(v3, h1f, lo1);
        yh1[j*4 + (l & 3)] = pack_bf16(h, h1f);
        yl1[j*4 + (l & 3)] = pack_bf16(lo0, lo1);
    }
}

// ---------------------------------------------------------------------------
// Flash attention (bf16x3, scores in log2 units). CTA = 64 q x 128 thr.
// K/V tiles double-buffered via cp.async. dyn smem = 73728 B.
// buffer b at b*36864: Kh +0, Kl +9216, Vh +18432, Vl +27648
// ---------------------------------------------------------------------------
__global__ __launch_bounds__(128, 1) void attn_mma_kernel()
{
    extern __shared__ char sbuf[];
    const uint32_t sbase = smem_u32(sbuf);

    const int tid = threadIdx.x;
    const int w   = tid >> 5;
    const int l   = tid & 31;
    const int b   = blockIdx.y;
    const int q0  = blockIdx.x * 64;

    const uint4* gkh = (const uint4*)(g_kh_hi + (size_t)b*SEQ*DK);
    const uint4* gkl = (const uint4*)(g_kh_lo + (size_t)b*SEQ*DK);
    const uint4* gvh = (const uint4*)(g_vh_hi + (size_t)b*SEQ*DK);
    const uint4* gvl = (const uint4*)(g_vh_lo + (size_t)b*SEQ*DK);

    // ---------------- Q fragments (once, via cp.async into buf0) ----------------
    {
        const uint4* gqh = (const uint4*)(g_qh_hi + (size_t)(b*SEQ + q0)*DK);
        const uint4* gql = (const uint4*)(g_qh_lo + (size_t)(b*SEQ + q0)*DK);
        #pragma unroll
        for (int it = 0; it < 4; it++) {
            int i = tid + it*128;
            int r = i >> 3, c = i & 7;
            uint32_t d = r*RSTRIDE_B + c*16;
            CP16(sbase + d, gqh + i);
            CP16(sbase + TILE_B + d, gql + i);
        }
        CP_COMMIT();
        CP_WAIT(0);
    }
    __syncthreads();

    uint32_t qa_h[4][4], qa_l[4][4];
    {
        int row = w*16 + (l & 7) + ((l >> 3) & 1)*8;
        int colb_off = ((l >> 3) & 2)*8;
        #pragma unroll
        for (int t = 0; t < 4; t++) {
            uint32_t a = sbase + row*RSTRIDE_B + t*32 + colb_off;
            LDSM_X4(qa_h[t][0], qa_h[t][1], qa_h[t][2], qa_h[t][3], a);
            LDSM_X4(qa_l[t][0], qa_l[t][1], qa_l[t][2], qa_l[t][3], a + TILE_B);
        }
    }
    __syncthreads();

    const int brow_off = (l & 7) + ((l >> 3) & 2)*4;
    const int bcol_off = ((l >> 3) & 1)*16;
    const int vrow_off = (l & 7) + ((l >> 3) & 1)*8;
    const int vcol_off = ((l >> 4) & 1)*16;

    float O[8][4];
    #pragma unroll
    for (int j = 0; j < 8; j++)
        #pragma unroll
        for (int i = 0; i < 4; i++) O[j][i] = 0.f;
    float mr[2] = {-1e30f, -1e30f};
    float lr[2] = {0.f, 0.f};

    const int q_lo = q0 + w*16 + (l >> 2);
    const int q_hi = q_lo + 8;

    // tile 0 -> buf0
    {
        #pragma unroll
        for (int it = 0; it < 4; it++) {
            int i = tid + it*128;
            int r = i >> 3, c = i & 7;
            uint32_t d = r*RSTRIDE_B + c*16;
            size_t gi = (size_t)r*8 + c;
            CP16(sbase + d,               gkh + gi);
            CP16(sbase + TILE_B + d,      gkl + gi);
            CP16(sbase + 2*TILE_B + d,    gvh + gi);
            CP16(sbase + 3*TILE_B + d,    gvl + gi);
        }
        CP_COMMIT();
    }

    for (int ti = 0; ti < SEQ/64; ti++) {
        const int k0 = ti*64;
        // prefetch next tile
        if (ti + 1 < SEQ/64) {
            uint32_t bo = sbase + ((ti+1)&1)*ABUF_B;
            #pragma unroll
            for (int it = 0; it < 4; it++) {
                int i = tid + it*128;
                int r = i >> 3, c = i & 7;
                uint32_t d = r*RSTRIDE_B + c*16;
                size_t gi = (size_t)(k0 + 64 + r)*8 + c;
                CP16(bo + d,               gkh + gi);
                CP16(bo + TILE_B + d,      gkl + gi);
                CP16(bo + 2*TILE_B + d,    gvh + gi);
                CP16(bo + 3*TILE_B + d,    gvl + gi);
            }
            CP_COMMIT();
            CP_WAIT(1);
        } else {
            CP_WAIT(0);
        }
        __syncthreads();

        const uint32_t ob = sbase + (ti&1)*ABUF_B;

        // ---- S = Q K^T (log2 units) ----
        float S[8][4];
        #pragma unroll
        for (int j = 0; j < 8; j++)
            #pragma unroll
            for (int i = 0; i < 4; i++) S[j][i] = 0.f;

        #pragma unroll
        for (int t = 0; t < 4; t++) {
            #pragma unroll
            for (int g = 0; g < 4; g++) {
                uint32_t a = ob + (g*16 + brow_off)*RSTRIDE_B + t*32 + bcol_off;
                uint32_t h0,h1,h2,h3, l0,l1,l2,l3;
                LDSM_X4(h0,h1,h2,h3, a);
                LDSM_X4(l0,l1,l2,l3, a + TILE_B);
                MMA16816(S[2*g],   qa_h[t][0],qa_h[t][1],qa_h[t][2],qa_h[t][3], h0,h1);
                MMA16816(S[2*g],   qa_h[t][0],qa_h[t][1],qa_h[t][2],qa_h[t][3], l0,l1);
                MMA16816(S[2*g],   qa_l[t][0],qa_l[t][1],qa_l[t][2],qa_l[t][3], h0,h1);
                MMA16816(S[2*g+1], qa_h[t][0],qa_h[t][1],qa_h[t][2],qa_h[t][3], h2,h3);
                MMA16816(S[2*g+1], qa_h[t][0],qa_h[t][1],qa_h[t][2],qa_h[t][3], l2,l3);
                MMA16816(S[2*g+1], qa_l[t][0],qa_l[t][1],qa_l[t][2],qa_l[t][3], h2,h3);
            }
        }

        // ---- mask ----
        {
            uint2 m0 = *(const uint2*)(g_mpack + (size_t)q_lo*(SEQ/32) + (k0 >> 5));
            uint2 m1 = *(const uint2*)(g_mpack + (size_t)q_hi*(SEQ/32) + (k0 >> 5));
            uint64_t w0 = ((uint64_t)m0.y << 32) | m0.x;
            uint64_t w1 = ((uint64_t)m1.y << 32) | m1.x;
            #pragma unroll
            for (int j = 0; j < 8; j++) {
                int c = j*8 + 2*(l & 3);
                if (!((w0 >> c) & 1))     S[j][0] = -1e9f;
                if (!((w0 >> (c+1)) & 1)) S[j][1] = -1e9f;
                if (!((w1 >> c) & 1))     S[j][2] = -1e9f;
                if (!((w1 >> (c+1)) & 1)) S[j][3] = -1e9f;
            }
        }

        // ---- online softmax (base-2) ----
        float mx0 = -1e30f, mx1 = -1e30f;
        #pragma unroll
        for (int j = 0; j < 8; j++) {
            mx0 = fmaxf(mx0, fmaxf(S[j][0], S[j][1]));
            mx1 = fmaxf(mx1, fmaxf(S[j][2], S[j][3]));
        }
        mx0 = fmaxf(mx0, __shfl_xor_sync(0xffffffffu, mx0, 1));
        mx0 = fmaxf(mx0, __shfl_xor_sync(0xffffffffu, mx0, 2));
        mx1 = fmaxf(mx1, __shfl_xor_sync(0xffffffffu, mx1, 1));
        mx1 = fmaxf(mx1, __shfl_xor_sync(0xffffffffu, mx1, 2));
        float mn0 = fmaxf(mr[0], mx0), mn1 = fmaxf(mr[1], mx1);
        float cr0 = exp2f(mr[0] - mn0), cr1 = exp2f(mr[1] - mn1);
        mr[0] = mn0; mr[1] = mn1;

        float ps0 = 0.f, ps1 = 0.f;
        uint32_t pa_h[4][4], pa_l[4][4];
        #pragma unroll
        for (int t = 0; t < 4; t++) {
            float p[8], lo[8];
            #pragma unroll
            for (int u = 0; u < 2; u++) {
                int j = 2*t + u;
                p[4*u+0] = exp2f(S[j][0] - mn0);
                p[4*u+1] = exp2f(S[j][1] - mn0);
                p[4*u+2] = exp2f(S[j][2] - mn1);
                p[4*u+3] = exp2f(S[j][3] - mn1);
                ps0 += p[4*u+0] + p[4*u+1];
                ps1 += p[4*u+2] + p[4*u+3];
            }
            #pragma unroll
            for (int e = 0; e < 8; e++) {
                float h, lw;
                split_bf16(p[e], h, lw);
                p[e] = h; lo[e] = lw;
            }
            pa_h[t][0] = pack_bf16(p[0], p[1]);
            pa_h[t][1] = pack_bf16(p[2], p[3]);
            pa_h[t][2] = pack_bf16(p[4], p[5]);
            pa_h[t][3] = pack_bf16(p[6], p[7]);
            pa_l[t][0] = pack_bf16(lo[0], lo[1]);
            pa_l[t][1] = pack_bf16(lo[2], lo[3]);
            pa_l[t][2] = pack_bf16(lo[4], lo[5]);
            pa_l[t][3] = pack_bf16(lo[6], lo[7]);
        }
        ps0 += __shfl_xor_sync(0xffffffffu, ps0, 1);
        ps0 += __shfl_xor_sync(0xffffffffu, ps0, 2);
        ps1 += __shfl_xor_sync(0xffffffffu, ps1, 1);
        ps1 += __shfl_xor_sync(0xffffffffu, ps1, 2);
        lr[0] = lr[0]*cr0 + ps0;
        lr[1] = lr[1]*cr1 + ps1;

        #pragma unroll
        for (int j = 0; j < 8; j++) {
            O[j][0] *= cr0; O[j][1] *= cr0;
            O[j][2] *= cr1; O[j][3] *= cr1;
        }

        // ---- O += P V ----
        #pragma unroll
        for (int t = 0; t < 4; t++) {
            #pragma unroll
            for (int g = 0; g < 4; g++) {
                uint32_t a = ob + 2*TILE_B + (t*16 + vrow_off)*RSTRIDE_B + g*32 + vcol_off;
                uint32_t h0,h1,h2,h3, l0,l1,l2,l3;
                LDSM_X4_T(h0,h1,h2,h3, a);
                LDSM_X4_T(l0,l1,l2,l3, a + TILE_B);
                MMA16816(O[2*g],   pa_h[t][0],pa_h[t][1],pa_h[t][2],pa_h[t][3], h0,h1);
                MMA16816(O[2*g],   pa_h[t][0],pa_h[t][1],pa_h[t][2],pa_h[t][3], l0,l1);
                MMA16816(O[2*g],   pa_l[t][0],pa_l[t][1],pa_l[t][2],pa_l[t][3], h0,h1);
                MMA16816(O[2*g+1], pa_h[t][0],pa_h[t][1],pa_h[t][2],pa_h[t][3], h2,h3);
                MMA16816(O[2*g+1], pa_h[t][0],pa_h[t][1],pa_h[t][2],pa_h[t][3], l2,l3);
                MMA16816(O[2*g+1], pa_l[t][0],pa_l[t][1],pa_l[t][2],pa_l[t][3], h2,h3);
            }
        }
        __syncthreads();
    }

    // ---- normalize + store bf16 hi/lo ----
    {
        float inv0 = 1.f / lr[0];
        float inv1 = 1.f / lr[1];
        uint32_t* yh0 = (uint32_t*)(g_aoh + (size_t)(b*SEQ + q_lo)*DK);
        uint32_t* yl0 = (uint32_t*)(g_aol + (size_t)(b*SEQ + q_lo)*DK);
        uint32_t* yh1 = (uint32_t*)(g_aoh + (size_t)(b*SEQ + q_hi)*DK);
        uint32_t* yl1 = (uint32_t*)(g_aol + (size_t)(b*SEQ + q_hi)*DK);
        #pragma unroll
        for (int j = 0; j < 8; j++) {
            float v0 = O[j][0]*inv0, v1 = O[j][1]*inv0;
            float v2 = O[j][2]*inv1, v3 = O[j][3]*inv1;
            float h0,lo0,h1f,lo1;
            split_bf16(v0, h0, lo0); split_bf16(v1, h1f, lo1);
            yh0[j*4 + (l & 3)] = pack_bf16(h0, h1f);
            yl0[j*4 + (l & 3)] = pack_bf16(lo0, lo1);
            split_bf16(v2, h0, lo0); split_bf16(v3, h1f, lo1);
            yh1[j*4 + (l & 3)] = pack_bf16(h0, h1f);
            yl1[j*4 + (l & 3)] = pack_bf16(lo0, lo1);
        }
    }
}

// ---------------------------------------------------------------------------
// Output projection: out[M,1024] = AO[M,64] @ Wo[1024,64]^T + bo
// CTA: 64 rows; Wo chunks double-buffered via cp.async.
// dyn smem: sAh 0, sAl 9216, Wbuf0 {18432,27648}, Wbuf1 {36864,46080}
// ---------------------------------------------------------------------------
__global__ __launch_bounds__(128, 1) void oproj_mma_kernel(
    const float* __restrict__ bo, float* __restrict__ out)
{
    extern __shared__ char psm[];
    const uint32_t sb = smem_u32(psm);

    const int tid = threadIdx.x;
    const int w = tid >> 5, l = tid & 31;
    const int row0 = blockIdx.x * 64;

    const __nv_bfloat16* gwh = g_wh + (size_t)3*65536;
    const __nv_bfloat16* gwl = g_wl + (size_t)3*65536;

    // stage A hi/lo + Wo chunk0 via cp.async
    {
        #pragma unroll
        for (int it = 0; it < 4; it++) {
            int i = tid + it*128;
            int r = i >> 3, c = i & 7;
            uint32_t d = r*RSTRIDE_B + c*16;
            CP16(sb + d,          ((const uint4*)(g_aoh + (size_t)(row0 + r)*DK)) + c);
            CP16(sb + TILE_B + d, ((const uint4*)(g_aol + (size_t)(row0 + r)*DK)) + c);
            CP16(sb + 2*TILE_B + d, ((const uint4*)(gwh + (size_t)r*DK)) + c);
            CP16(sb + 3*TILE_B + d, ((const uint4*)(gwl + (size_t)r*DK)) + c);
        }
        CP_COMMIT();
        CP_WAIT(0);
    }
    __syncthreads();

    uint32_t oa_h[4][4], oa_l[4][4];
    {
        int row = w*16 + (l & 7) + ((l >> 3) & 1)*8;
        int colb_off = ((l >> 3) & 2)*8;
        #pragma unroll
        for (int t = 0; t < 4; t++) {
            uint32_t a = sb + row*RSTRIDE_B + t*32 + colb_off;
            LDSM_X4(oa_h[t][0], oa_h[t][1], oa_h[t][2], oa_h[t][3], a);
            LDSM_X4(oa_l[t][0], oa_l[t][1], oa_l[t][2], oa_l[t][3], a + TILE_B);
        }
    }

    const int brow  = (l & 7) + ((l >> 3) & 2)*4;
    const int bcolb = ((l >> 3) & 1)*16;
    const int row_lo = row0 + w*16 + (l >> 2);
    const int row_hi = row_lo + 8;

    for (int nc = 0; nc < 16; nc++) {
        const int n0 = nc*64;
        if (nc + 1 < 16) {
            uint32_t wb = sb + 2*TILE_B + ((nc+1)&1)*2*TILE_B;
            #pragma unroll
            for (int it = 0; it < 4; it++) {
                int i = tid + it*128;
                int r = i >> 3, c = i & 7;
                uint32_t d = r*RSTRIDE_B + c*16;
                CP16(wb + d,          ((const uint4*)(gwh + (size_t)(n0 + 64 + r)*DK)) + c);
                CP16(wb + TILE_B + d, ((const uint4*)(gwl + (size_t)(n0 + 64 + r)*DK)) + c);
            }
            CP_COMMIT();
            CP_WAIT(1);
        } else {
            CP_WAIT(0);
        }
        __syncthreads();

        const uint32_t aWh = sb + 2*TILE_B + (nc&1)*2*TILE_B;
        float C[8][4];
        #pragma unroll
        for (int j = 0; j < 8; j++)
            #pragma unroll
            for (int i = 0; i < 4; i++) C[j][i] = 0.f;

        #pragma unroll
        for (int t = 0; t < 4; t++) {
            #pragma unroll
            for (int g = 0; g < 4; g++) {
                uint32_t ba = aWh + (g*16 + brow)*RSTRIDE_B + t*32 + bcolb;
                uint32_t h0,h1,h2,h3, w0,w1,w2,w3;
                LDSM_X4(h0,h1,h2,h3, ba);
                LDSM_X4(w0,w1,w2,w3, ba + TILE_B);
                MMA16816(C[2*g],   oa_h[t][0],oa_h[t][1],oa_h[t][2],oa_h[t][3], h0,h1);
                MMA16816(C[2*g],   oa_h[t][0],oa_h[t][1],oa_h[t][2],oa_h[t][3], w0,w1);
                MMA16816(C[2*g],   oa_l[t][0],oa_l[t][1],oa_l[t][2],oa_l[t][3], h0,h1);
                MMA16816(C[2*g+1], oa_h[t][0],oa_h[t][1],oa_h[t][2],oa_h[t][3], h2,h3);
                MMA16816(C[2*g+1], oa_h[t][0],oa_h[t][1],oa_h[t][2],oa_h[t][3], w2,w3);
                MMA16816(C[2*g+1], oa_l[t][0],oa_l[t][1],oa_l[t][2],oa_l[t][3], h2,h3);
            }
        }

        float2* po0 = (float2*)(out + (size_t)row_lo*DM + n0);
        float2* po1 = (float2*)(out + (size_t)row_hi*DM + n0);
        #pragma unroll
        for (int j = 0; j < 8; j++) {
            int c = j*8 + 2*(l & 3);
            float b0v = bo[n0 + c], b1v = bo[n0 + c + 1];
            float2 v0 = { C[j][0] + b0v, C[j][1] + b1v };
            float2 v1 = { C[j][2] + b0v, C[j][3] + b1v };
            po0[j*4 + (l & 3)] = v0;
            po1[j*4 + (l & 3)] = v1;
        }
        __syncthreads();
    }
}

// ---------------------------------------------------------------------------
extern "C" void kernel_launch(void* const* d_in, const int* in_sizes, int n_in,
                              void* d_out, int out_size)
{
    const float* q    = (const float*)d_in[0];
    const float* k    = (const float*)d_in[1];
    const float* v    = (const float*)d_in[2];
    const int*   mask = (const int*)  d_in[3];
    const float* Wq   = (const float*)d_in[4];
    const float* bq   = (const float*)d_in[5];
    const float* Wk   = (const float*)d_in[6];
    const float* bk   = (const float*)d_in[7];
    const float* Wv   = (const float*)d_in[8];
    const float* bv   = (const float*)d_in[9];
    const float* Wo   = (const float*)d_in[10];
    const float* bo   = (const float*)d_in[11];
    float* out = (float*)d_out;

    const int proj_smem = 6*TILE_B;    // 55296
    const int attn_smem = 2*ABUF_B;    // 73728
    cudaFuncSetAttribute(proj_mma_kernel,
                         cudaFuncAttributeMaxDynamicSharedMemorySize, proj_smem);
    cudaFuncSetAttribute(attn_mma_kernel,
                         cudaFuncAttributeMaxDynamicSharedMemorySize, attn_smem);
    cudaFuncSetAttribute(oproj_mma_kernel,
                         cudaFuncAttributeMaxDynamicSharedMemorySize, proj_smem);

    pack_mask_kernel<<<SEQ*SEQ/32/8, 256>>>(mask);
    split_w_kernel<<<dim3(64, 4), 256>>>(Wq, Wk, Wv, Wo);

    proj_mma_kernel<<<dim3(MTOT/64, 3), 128, proj_smem>>>(q, k, v, bq, bk, bv);

    attn_mma_kernel<<<dim3(SEQ/64, BB), 128, attn_smem>>>();

    oproj_mma_kernel<<<MTOT/64, 128, proj_smem>>>(bo, out);
}